// round 6
// baseline (speedup 1.0000x reference)
#include <cuda_runtime.h>
#include <cuda_bf16.h>
#include <math.h>
#include <stdint.h>

#define M_TOT 8192
#define C_DIM 1024
#define S_LEN 2048
#define NB 4

// ---------------- static scratch (no allocations allowed) ----------------
// fp32
__device__ float g_h0[M_TOT * C_DIM];
__device__ float g_att[M_TOT * C_DIM];
__device__ float g_pred[M_TOT * C_DIM];
// interleaved hi/lo bf16 buffers: layout per [R,K] matrix:
//   elem (r,k): hi at r*2K + (k>>3)*16 + (k&7), lo at +8
#define W_FCIN 0
#define W_QKV  2097152
#define W_PROJ 27262976
#define W_FCOUT 35651584
#define W_IL_TOTAL 37748736
__device__ __nv_bfloat16 g_w_il[W_IL_TOTAL];
__device__ __nv_bfloat16 g_x_il[2L * M_TOT * C_DIM];
__device__ __nv_bfloat16 g_a_il[2L * M_TOT * C_DIM];
__device__ __nv_bfloat16 g_qkv_il[2L * M_TOT * 3 * C_DIM];
__device__ __nv_bfloat16 g_vt_il[2L * NB * C_DIM * S_LEN];
__device__ __nv_bfloat16 g_sc_il[2L * NB * S_LEN * S_LEN];
__device__ __nv_bfloat16 g_sm_il[2L * M_TOT * C_DIM];

// ---------------- helpers ----------------
__device__ __forceinline__ uint32_t smem_u32(const void* p) {
    uint32_t a;
    asm("{ .reg .u64 t; cvta.to.shared.u64 t, %1; cvt.u32.u64 %0, t; }" : "=r"(a) : "l"(p));
    return a;
}
__device__ __forceinline__ long il_idx(long r, int k, int K) {
    return r * (2L * K) + ((k >> 3) << 4) + (k & 7);
}
__device__ __forceinline__ float gelu_f(float x) {
    return 0.5f * x * (1.0f + erff(x * 0.70710678118654752f));
}
__device__ __forceinline__ uint32_t bf2_bits(__nv_bfloat162 v) {
    return *reinterpret_cast<uint32_t*>(&v);
}
__device__ __forceinline__ void split4(float4 f, uint2& hi, uint2& lo) {
    __nv_bfloat162 h01 = __floats2bfloat162_rn(f.x, f.y);
    __nv_bfloat162 h23 = __floats2bfloat162_rn(f.z, f.w);
    float2 g01 = __bfloat1622float2(h01), g23 = __bfloat1622float2(h23);
    __nv_bfloat162 l01 = __floats2bfloat162_rn(f.x - g01.x, f.y - g01.y);
    __nv_bfloat162 l23 = __floats2bfloat162_rn(f.z - g23.x, f.w - g23.y);
    hi = make_uint2(bf2_bits(h01), bf2_bits(h23));
    lo = make_uint2(bf2_bits(l01), bf2_bits(l23));
}
__device__ __forceinline__ void split2(float a, float b, uint32_t& hi, uint32_t& lo) {
    __nv_bfloat162 h = __floats2bfloat162_rn(a, b);
    float2 g = __bfloat1622float2(h);
    __nv_bfloat162 l = __floats2bfloat162_rn(a - g.x, b - g.y);
    hi = bf2_bits(h); lo = bf2_bits(l);
}
__device__ __forceinline__ void ldsm4(uint32_t* r, uint32_t addr) {
    asm volatile("ldmatrix.sync.aligned.m8n8.x4.shared.b16 {%0,%1,%2,%3}, [%4];"
        : "=r"(r[0]), "=r"(r[1]), "=r"(r[2]), "=r"(r[3]) : "r"(addr));
}
__device__ __forceinline__ void mma16816(float* d, const uint32_t* a, const uint32_t* b) {
    asm volatile("mma.sync.aligned.m16n8k16.row.col.f32.bf16.bf16.f32 "
        "{%0,%1,%2,%3}, {%4,%5,%6,%7}, {%8,%9}, {%0,%1,%2,%3};"
        : "+f"(d[0]), "+f"(d[1]), "+f"(d[2]), "+f"(d[3])
        : "r"(a[0]), "r"(a[1]), "r"(a[2]), "r"(a[3]), "r"(b[0]), "r"(b[1]));
}
#define CP16(dst, src) \
    asm volatile("cp.async.cg.shared.global [%0], [%1], 16;" :: "r"(dst), "l"(src) : "memory")
#define CP_COMMIT() asm volatile("cp.async.commit_group;" ::: "memory")
#define CP_WAIT2() asm volatile("cp.async.wait_group 2;" ::: "memory")
#define CP_WAIT0() asm volatile("cp.async.wait_group 0;" ::: "memory")

// SMEM stage: 4 tiles (AH, AL, BH, BL), each 128 rows x 32 bf16, row stride 80B.
#define ROW_B 80
#define TILE_B 10240
#define STAGE_B 40960
#define NSTAGE 4
#define SM_TOT (NSTAGE * STAGE_B)

// D[M,N] = epi(scale * A[M,K] @ B[N,K]^T), interleaved-split bf16 inputs, HMMA,
// 4-stage cp.async. CTA tile 128x128, BK=32, 256 thr = 8 warps (2M x 4N), warp 64x32.
__global__ void __launch_bounds__(256) gemm_sp(
    const __nv_bfloat16* __restrict__ A, const __nv_bfloat16* __restrict__ B,
    float* __restrict__ C, __nv_bfloat16* __restrict__ O,
    int K, int lda, int ldb, int ldc,
    long sA, long sB, long sC,
    const float* __restrict__ bias, const float* __restrict__ residual,
    float scale, int act, int pe)
{
    extern __shared__ char sm[];
    uint32_t sb = smem_u32(sm);

    int tid = threadIdx.x, wid = tid >> 5, lane = tid & 31;
    long bz = blockIdx.z;
    const char* Ab = (const char*)(A + bz * 2 * sA);
    const char* Bb = (const char*)(B + bz * 2 * sB);
    if (C) C += bz * sC;
    if (O) O += bz * 2 * sC;
    const float* res = residual ? residual + bz * sC : nullptr;
    long row0 = (long)blockIdx.y * 128, col0 = (long)blockIdx.x * 128;

    int wm = wid >> 2, wn = wid & 3;
    int m0w = wm * 64, n0w = wn * 32;

    float acc[4][4][4];
#pragma unroll
    for (int i = 0; i < 4; i++)
#pragma unroll
        for (int j = 0; j < 4; j++)
#pragma unroll
            for (int e = 0; e < 4; e++) acc[i][j][e] = 0.f;

    // loader: row = tid>>1, groups sg..sg+1 of the 4 8-elem k-groups per chunk
    const int r_ld = tid >> 1;
    const int sg = (tid & 1) * 2;
    const int NC = K >> 5;

    const char* a_src = Ab + (row0 + r_ld) * (4L * lda) + sg * 32;
    const char* b_src = Bb + (col0 + r_ld) * (4L * ldb) + sg * 32;
    const uint32_t stA = sb + r_ld * ROW_B + sg * 16;
    const uint32_t stB = stA + 2 * TILE_B;

    auto issue = [&](int c) {
        const char* sa = a_src + (long)c * 128;
        const char* sbp = b_src + (long)c * 128;
        uint32_t dA = stA + (c & 3) * STAGE_B;
        uint32_t dB = stB + (c & 3) * STAGE_B;
        CP16(dA, sa);                        // hi g0
        CP16(dA + 16, sa + 32);              // hi g1
        CP16(dA + TILE_B, sa + 16);          // lo g0
        CP16(dA + TILE_B + 16, sa + 48);     // lo g1
        CP16(dB, sbp);
        CP16(dB + 16, sbp + 32);
        CP16(dB + TILE_B, sbp + 16);
        CP16(dB + TILE_B + 16, sbp + 48);
    };

    // ldmatrix addresses (stage 0; add (c&3)*STAGE_B)
    uint32_t a_addr_h[4], a_addr_l[4], b_addr_h[2], b_addr_l[2];
#pragma unroll
    for (int i = 0; i < 4; i++) {
        uint32_t r = m0w + i * 16 + (lane & 15);
        uint32_t byt = r * ROW_B + (lane >> 4) * 16;
        a_addr_h[i] = sb + byt;
        a_addr_l[i] = sb + TILE_B + byt;
    }
#pragma unroll
    for (int jp = 0; jp < 2; jp++) {        // pair of n-tiles (2j, 2j+1)
        uint32_t r = n0w + jp * 16 + (lane >> 4) * 8 + (lane & 7);
        uint32_t byt = r * ROW_B + ((lane >> 3) & 1) * 16;
        b_addr_h[jp] = sb + 2 * TILE_B + byt;
        b_addr_l[jp] = sb + 3 * TILE_B + byt;
    }

    issue(0); CP_COMMIT();
    issue(1); CP_COMMIT();
    issue(2); CP_COMMIT();

    for (int c = 0; c < NC; c++) {
        CP_WAIT2();
        __syncthreads();
        if (c + 3 < NC) issue(c + 3);
        CP_COMMIT();
        uint32_t bofs = (c & 3) * STAGE_B;
#pragma unroll
        for (int ks = 0; ks < 2; ks++) {
            uint32_t ah[4][4], al[4][4], bh[2][4], bl[2][4];
#pragma unroll
            for (int i = 0; i < 4; i++) {
                ldsm4(ah[i], a_addr_h[i] + bofs + ks * 32);
                ldsm4(al[i], a_addr_l[i] + bofs + ks * 32);
            }
#pragma unroll
            for (int jp = 0; jp < 2; jp++) {
                ldsm4(bh[jp], b_addr_h[jp] + bofs + ks * 32);
                ldsm4(bl[jp], b_addr_l[jp] + bofs + ks * 32);
            }
#pragma unroll
            for (int i = 0; i < 4; i++)
#pragma unroll
                for (int j = 0; j < 4; j++)
                    mma16816(acc[i][j], ah[i], &bh[j >> 1][(j & 1) * 2]);
#pragma unroll
            for (int i = 0; i < 4; i++)
#pragma unroll
                for (int j = 0; j < 4; j++)
                    mma16816(acc[i][j], ah[i], &bl[j >> 1][(j & 1) * 2]);
#pragma unroll
            for (int i = 0; i < 4; i++)
#pragma unroll
                for (int j = 0; j < 4; j++)
                    mma16816(acc[i][j], al[i], &bh[j >> 1][(j & 1) * 2]);
        }
    }
    CP_WAIT0();

    // epilogue: thread holds C[r1][cc..cc+1], C[r1+8][cc..cc+1] per (i,j)
#pragma unroll
    for (int i = 0; i < 4; i++) {
        long r1 = row0 + m0w + i * 16 + (lane >> 2);
        long r2 = r1 + 8;
#pragma unroll
        for (int j = 0; j < 4; j++) {
            long cc = col0 + n0w + j * 8 + 2 * (lane & 3);
            float2 bi = bias ? *(const float2*)(bias + cc) : make_float2(0.f, 0.f);
            float v0 = acc[i][j][0] * scale + bi.x;
            float v1 = acc[i][j][1] * scale + bi.y;
            float v2 = acc[i][j][2] * scale + bi.x;
            float v3 = acc[i][j][3] * scale + bi.y;
            if (act) { v0 = gelu_f(v0); v1 = gelu_f(v1); v2 = gelu_f(v2); v3 = gelu_f(v3); }
            if (res) {
                float2 q1 = *(const float2*)(res + r1 * ldc + cc);
                float2 q2 = *(const float2*)(res + r2 * ldc + cc);
                v0 += q1.x; v1 += q1.y; v2 += q2.x; v3 += q2.y;
            }
            if (pe) {
                float d0 = expf((float)cc * (-2.0f / 1024.0f) * 6.9077552789821370521f);
                float d1 = expf((float)(cc + 1) * (-2.0f / 1024.0f) * 6.9077552789821370521f);
                int s1 = (int)(r1 & (S_LEN - 1)), s2 = (int)(r2 & (S_LEN - 1));
                float a10 = s1 * d0, a11 = s1 * d1, a20 = s2 * d0, a21 = s2 * d1;
                v0 += (s1 & 1) ? cosf(a10) : sinf(a10);
                v1 += (s1 & 1) ? cosf(a11) : sinf(a11);
                v2 += (s2 & 1) ? cosf(a20) : sinf(a20);
                v3 += (s2 & 1) ? cosf(a21) : sinf(a21);
            }
            if (C) {
                *(float2*)(C + r1 * ldc + cc) = make_float2(v0, v1);
                *(float2*)(C + r2 * ldc + cc) = make_float2(v2, v3);
            }
            if (O) {
                uint32_t h, l;
                long i1 = il_idx(r1, (int)cc, ldc), i2 = il_idx(r2, (int)cc, ldc);
                split2(v0, v1, h, l);
                *(uint32_t*)(O + i1) = h;
                *(uint32_t*)(O + i1 + 8) = l;
                split2(v2, v3, h, l);
                *(uint32_t*)(O + i2) = h;
                *(uint32_t*)(O + i2 + 8) = l;
            }
        }
    }
}

// fp32 [R,1024] -> interleaved split, grid-stride over float4s
__global__ void split_kernel(const float* __restrict__ src,
                             __nv_bfloat16* __restrict__ dst, long n4)
{
    long i = (long)blockIdx.x * blockDim.x + threadIdx.x;
    long stride = (long)gridDim.x * blockDim.x;
    for (; i < n4; i += stride) {
        float4 f = ((const float4*)src)[i];
        uint2 h, l;
        split4(f, h, l);
        long r = i >> 8;              // 256 float4 per row (K=1024)
        int k0 = (int)(i & 255) * 4;
        long o = il_idx(r, k0, 1024);
        *(uint2*)(dst + o) = h;
        *(uint2*)(dst + o + 8) = l;
    }
}

// vt[b][c][s] = qkv[b,s,2C+c], interleaved form both sides
__global__ void transpose_v_bf(const __nv_bfloat16* __restrict__ q_il,
                               __nv_bfloat16* __restrict__ v_il)
{
    __shared__ __nv_bfloat16 th[32][34], tl[32][34];
    int b = blockIdx.z;
    int s0 = blockIdx.x * 32, c0 = blockIdx.y * 32;
    int tx = threadIdx.x, ty = threadIdx.y;
    const __nv_bfloat16* src = q_il + (long)b * S_LEN * 2 * 3 * C_DIM;
#pragma unroll
    for (int i = 0; i < 32; i += 8) {
        long o = il_idx((long)(s0 + ty + i), 2 * C_DIM + c0 + tx, 3 * C_DIM);
        th[ty + i][tx] = src[o];
        tl[ty + i][tx] = src[o + 8];
    }
    __syncthreads();
    __nv_bfloat16* dst = v_il + (long)b * C_DIM * 2 * S_LEN;
#pragma unroll
    for (int i = 0; i < 32; i += 8) {
        long o = il_idx((long)(c0 + ty + i), s0 + tx, S_LEN);
        dst[o] = th[tx][ty + i];
        dst[o + 8] = tl[tx][ty + i];
    }
}

// layernorm over last dim (1024), fp32 in -> interleaved split out
__global__ void layernorm_kernel(const float* __restrict__ h,
                                 const float* __restrict__ g,
                                 const float* __restrict__ b,
                                 __nv_bfloat16* __restrict__ o_il)
{
    __shared__ float sa[8], sb2[8];
    long row = blockIdx.x;
    const float* p = h + row * C_DIM;
    int tid = threadIdx.x;
    float v[4];
    float s1 = 0.f, s2 = 0.f;
#pragma unroll
    for (int i = 0; i < 4; i++) {
        v[i] = p[tid + i * 256];
        s1 += v[i];
        s2 += v[i] * v[i];
    }
#pragma unroll
    for (int o = 16; o > 0; o >>= 1) {
        s1 += __shfl_down_sync(0xffffffffu, s1, o);
        s2 += __shfl_down_sync(0xffffffffu, s2, o);
    }
    int lane = tid & 31, w = tid >> 5;
    if (lane == 0) { sa[w] = s1; sb2[w] = s2; }
    __syncthreads();
    if (tid < 32) {
        s1 = (tid < 8) ? sa[tid] : 0.f;
        s2 = (tid < 8) ? sb2[tid] : 0.f;
#pragma unroll
        for (int o = 4; o > 0; o >>= 1) {
            s1 += __shfl_down_sync(0xffffffffu, s1, o);
            s2 += __shfl_down_sync(0xffffffffu, s2, o);
        }
        if (tid == 0) { sa[0] = s1; sb2[0] = s2; }
    }
    __syncthreads();
    float mu = sa[0] * (1.0f / 1024.0f);
    float var = sb2[0] * (1.0f / 1024.0f) - mu * mu;
    float inv = rsqrtf(var + 1e-5f);
#pragma unroll
    for (int i = 0; i < 4; i++) {
        int c = tid + i * 256;
        float y = (v[i] - mu) * inv * g[c] + b[c];
        __nv_bfloat16 hb = __float2bfloat16_rn(y);
        long o = il_idx(row, c, C_DIM);
        o_il[o] = hb;
        o_il[o + 8] = __float2bfloat16_rn(y - __bfloat162float(hb));
    }
}

// softmax over last dim (1024), fp32 in -> interleaved split out
__global__ void softmax_kernel(const float* __restrict__ att,
                               __nv_bfloat16* __restrict__ o_il)
{
    __shared__ float sh[8];
    long row = blockIdx.x;
    const float* p = att + row * C_DIM;
    int tid = threadIdx.x;
    float v[4];
    float m = -INFINITY;
#pragma unroll
    for (int i = 0; i < 4; i++) {
        v[i] = p[tid + i * 256];
        m = fmaxf(m, v[i]);
    }
#pragma unroll
    for (int o = 16; o > 0; o >>= 1)
        m = fmaxf(m, __shfl_down_sync(0xffffffffu, m, o));
    int lane = tid & 31, w = tid >> 5;
    if (lane == 0) sh[w] = m;
    __syncthreads();
    if (tid < 32) {
        m = (tid < 8) ? sh[tid] : -INFINITY;
#pragma unroll
        for (int o = 4; o > 0; o >>= 1)
            m = fmaxf(m, __shfl_down_sync(0xffffffffu, m, o));
        if (tid == 0) sh[0] = m;
    }
    __syncthreads();
    m = sh[0];
    __syncthreads();
    float e[4];
    float s = 0.f;
#pragma unroll
    for (int i = 0; i < 4; i++) {
        e[i] = expf(v[i] - m);
        s += e[i];
    }
#pragma unroll
    for (int o = 16; o > 0; o >>= 1)
        s += __shfl_down_sync(0xffffffffu, s, o);
    if (lane == 0) sh[w] = s;
    __syncthreads();
    if (tid < 32) {
        s = (tid < 8) ? sh[tid] : 0.f;
#pragma unroll
        for (int o = 4; o > 0; o >>= 1)
            s += __shfl_down_sync(0xffffffffu, s, o);
        if (tid == 0) sh[0] = s;
    }
    __syncthreads();
    float inv = 1.0f / sh[0];
#pragma unroll
    for (int i = 0; i < 4; i++) {
        int c = tid + i * 256;
        float y = e[i] * inv;
        __nv_bfloat16 hb = __float2bfloat16_rn(y);
        long o = il_idx(row, c, C_DIM);
        o_il[o] = hb;
        o_il[o + 8] = __float2bfloat16_rn(y - __bfloat162float(hb));
    }
}

static void launch_gemm(const __nv_bfloat16* A, const __nv_bfloat16* B,
                        float* C, __nv_bfloat16* O,
                        int M, int N, int K, int lda, int ldb, int ldc,
                        long sA, long sB, long sC, int batches,
                        const float* bias, const float* residual,
                        float scale, int act, int pe)
{
    dim3 grid(N / 128, M / 128, batches);
    gemm_sp<<<grid, 256, SM_TOT>>>(A, B, C, O, K, lda, ldb, ldc,
                                   sA, sB, sC, bias, residual, scale, act, pe);
}

extern "C" void kernel_launch(void* const* d_in, const int* in_sizes, int n_in,
                              void* d_out, int out_size)
{
    const float* x        = (const float*)d_in[0];
    const float* fc_in_w  = (const float*)d_in[1];
    const float* fc_in_b  = (const float*)d_in[2];
    const float* ln_g     = (const float*)d_in[3];
    const float* ln_b     = (const float*)d_in[4];
    const float* qkv_w    = (const float*)d_in[5];
    const float* qkv_b    = (const float*)d_in[6];
    const float* proj_w   = (const float*)d_in[7];
    const float* proj_b   = (const float*)d_in[8];
    const float* fc_out_w = (const float*)d_in[9];
    const float* fc_out_b = (const float*)d_in[10];
    float* out = (float*)d_out;

    cudaFuncSetAttribute(gemm_sp, cudaFuncAttributeMaxDynamicSharedMemorySize, SM_TOT);

    __nv_bfloat16 *wil, *xil, *ail, *qil, *vil, *scil, *smil;
    float *h0, *att, *pred;
    cudaGetSymbolAddress((void**)&wil, g_w_il);
    cudaGetSymbolAddress((void**)&xil, g_x_il);
    cudaGetSymbolAddress((void**)&ail, g_a_il);
    cudaGetSymbolAddress((void**)&qil, g_qkv_il);
    cudaGetSymbolAddress((void**)&vil, g_vt_il);
    cudaGetSymbolAddress((void**)&scil, g_sc_il);
    cudaGetSymbolAddress((void**)&smil, g_sm_il);
    cudaGetSymbolAddress((void**)&h0, g_h0);
    cudaGetSymbolAddress((void**)&att, g_att);
    cudaGetSymbolAddress((void**)&pred, g_pred);

    // split inputs/weights (all have K=1024 rows)
    split_kernel<<<512, 256>>>(x, xil, (long)M_TOT * C_DIM / 4);
    split_kernel<<<256, 256>>>(fc_in_w, wil + W_FCIN, (long)C_DIM * C_DIM / 4);
    split_kernel<<<1024, 256>>>(qkv_w, wil + W_QKV, (long)4 * 3 * C_DIM * C_DIM / 4);
    split_kernel<<<512, 256>>>(proj_w, wil + W_PROJ, (long)4 * C_DIM * C_DIM / 4);
    split_kernel<<<256, 256>>>(fc_out_w, wil + W_FCOUT, (long)C_DIM * C_DIM / 4);

    // h0 = x @ fc_in_w^T + fc_in_b    (fp32 out only)
    launch_gemm(xil, wil + W_FCIN, h0, nullptr,
                M_TOT, C_DIM, C_DIM, C_DIM, C_DIM, C_DIM, 0, 0, 0, 1,
                fc_in_b, nullptr, 1.0f, 0, 0);

    // a = split(layernorm(h0))
    layernorm_kernel<<<M_TOT, 256>>>(h0, ln_g, ln_b, ail);

    for (int i = 0; i < 4; i++) {
        long wq = W_QKV + 2L * i * 3 * C_DIM * C_DIM;
        long wp = W_PROJ + 2L * i * C_DIM * C_DIM;

        // qkv = split(gelu(a @ qkv_w[i]^T + qkv_b[i]))
        launch_gemm(ail, wil + wq, nullptr, qil,
                    M_TOT, 3 * C_DIM, C_DIM, C_DIM, C_DIM, 3 * C_DIM, 0, 0, 0, 1,
                    qkv_b + (long)i * 3 * C_DIM, nullptr, 1.0f, 1, 0);

        // vt = transpose of v (interleaved)
        transpose_v_bf<<<dim3(S_LEN / 32, C_DIM / 32, NB), dim3(32, 8)>>>(qil, vil);

        // scores = split(q @ k^T / C)  (batched; k-part = +2048 il elems)
        launch_gemm(qil, qil + 2048, nullptr, scil,
                    S_LEN, S_LEN, C_DIM, 3 * C_DIM, 3 * C_DIM, S_LEN,
                    (long)S_LEN * 3 * C_DIM, (long)S_LEN * 3 * C_DIM, (long)S_LEN * S_LEN,
                    NB, nullptr, nullptr, 1.0f / 1024.0f, 0, 0);

        // att = scores @ vt^T   (fp32 out, batched)
        launch_gemm(scil, vil, att, nullptr,
                    S_LEN, C_DIM, S_LEN, S_LEN, S_LEN, C_DIM,
                    (long)S_LEN * S_LEN, (long)C_DIM * S_LEN, (long)S_LEN * C_DIM,
                    NB, nullptr, nullptr, 1.0f, 0, 0);

        // sm = split(softmax(att))
        softmax_kernel<<<M_TOT, 256>>>(att, smil);

        // a = split(gelu(sm @ proj_w[i]^T + proj_b[i]) [+ pred]); fp32 pred copy on i==0
        launch_gemm(smil, wil + wp, (i == 0) ? pred : nullptr, ail,
                    M_TOT, C_DIM, C_DIM, C_DIM, C_DIM, C_DIM, 0, 0, 0, 1,
                    proj_b + (long)i * C_DIM, (i == 0) ? nullptr : pred, 1.0f, 1, 0);
    }

    // out = a @ fc_out_w^T + fc_out_b + pose_enc
    launch_gemm(ail, wil + W_FCOUT, out, nullptr,
                M_TOT, C_DIM, C_DIM, C_DIM, C_DIM, C_DIM, 0, 0, 0, 1,
                fc_out_b, nullptr, 1.0f, 0, 1);
}

// round 7
// speedup vs baseline: 1.0918x; 1.0918x over previous
#include <cuda_runtime.h>
#include <cuda_bf16.h>
#include <math.h>
#include <stdint.h>

#define M_TOT 8192
#define C_DIM 1024
#define S_LEN 2048
#define NB 4

// ---------------- static scratch (no allocations allowed) ----------------
// fp32
__device__ float g_h0[M_TOT * C_DIM];
__device__ float g_att[M_TOT * C_DIM];
__device__ float g_pred[M_TOT * C_DIM];
// interleaved hi/lo bf16 buffers: elem (r,k): hi at r*2K + (k>>3)*16 + (k&7), lo at +8
#define W_FCIN 0
#define W_QKV  2097152
#define W_PROJ 27262976
#define W_FCOUT 35651584
#define W_IL_TOTAL 37748736
__device__ __nv_bfloat16 g_w_il[W_IL_TOTAL];
__device__ __nv_bfloat16 g_x_il[2L * M_TOT * C_DIM];
__device__ __nv_bfloat16 g_a_il[2L * M_TOT * C_DIM];
__device__ __nv_bfloat16 g_qkv_il[2L * M_TOT * 3 * C_DIM];
__device__ __nv_bfloat16 g_vt_il[2L * NB * C_DIM * S_LEN];
__device__ __nv_bfloat16 g_sc_il[2L * NB * S_LEN * S_LEN];
__device__ __nv_bfloat16 g_sm_il[2L * M_TOT * C_DIM];

// ---------------- helpers ----------------
__device__ __forceinline__ uint32_t smem_u32(const void* p) {
    uint32_t a;
    asm("{ .reg .u64 t; cvta.to.shared.u64 t, %1; cvt.u32.u64 %0, t; }" : "=r"(a) : "l"(p));
    return a;
}
__device__ __forceinline__ long il_idx(long r, int k, int K) {
    return r * (2L * K) + ((k >> 3) << 4) + (k & 7);
}
__device__ __forceinline__ float gelu_f(float x) {
    return 0.5f * x * (1.0f + erff(x * 0.70710678118654752f));
}
__device__ __forceinline__ uint32_t bf2_bits(__nv_bfloat162 v) {
    return *reinterpret_cast<uint32_t*>(&v);
}
__device__ __forceinline__ void split4(float4 f, uint2& hi, uint2& lo) {
    __nv_bfloat162 h01 = __floats2bfloat162_rn(f.x, f.y);
    __nv_bfloat162 h23 = __floats2bfloat162_rn(f.z, f.w);
    float2 g01 = __bfloat1622float2(h01), g23 = __bfloat1622float2(h23);
    __nv_bfloat162 l01 = __floats2bfloat162_rn(f.x - g01.x, f.y - g01.y);
    __nv_bfloat162 l23 = __floats2bfloat162_rn(f.z - g23.x, f.w - g23.y);
    hi = make_uint2(bf2_bits(h01), bf2_bits(h23));
    lo = make_uint2(bf2_bits(l01), bf2_bits(l23));
}
__device__ __forceinline__ void split2(float a, float b, uint32_t& hi, uint32_t& lo) {
    __nv_bfloat162 h = __floats2bfloat162_rn(a, b);
    float2 g = __bfloat1622float2(h);
    __nv_bfloat162 l = __floats2bfloat162_rn(a - g.x, b - g.y);
    hi = bf2_bits(h); lo = bf2_bits(l);
}
__device__ __forceinline__ void ldsm4(uint32_t* r, uint32_t addr) {
    asm volatile("ldmatrix.sync.aligned.m8n8.x4.shared.b16 {%0,%1,%2,%3}, [%4];"
        : "=r"(r[0]), "=r"(r[1]), "=r"(r[2]), "=r"(r[3]) : "r"(addr));
}
__device__ __forceinline__ void mma16816(float* d, const uint32_t* a, const uint32_t* b) {
    asm volatile("mma.sync.aligned.m16n8k16.row.col.f32.bf16.bf16.f32 "
        "{%0,%1,%2,%3}, {%4,%5,%6,%7}, {%8,%9}, {%0,%1,%2,%3};"
        : "+f"(d[0]), "+f"(d[1]), "+f"(d[2]), "+f"(d[3])
        : "r"(a[0]), "r"(a[1]), "r"(a[2]), "r"(a[3]), "r"(b[0]), "r"(b[1]));
}
#define CP16(dst, src) \
    asm volatile("cp.async.cg.shared.global [%0], [%1], 16;" :: "r"(dst), "l"(src) : "memory")
#define CP_COMMIT() asm volatile("cp.async.commit_group;" ::: "memory")
#define CP_WAIT1() asm volatile("cp.async.wait_group 1;" ::: "memory")
#define CP_WAIT0() asm volatile("cp.async.wait_group 0;" ::: "memory")

// Stage: 4 tiles (AH, AL, BH, BL), 128 rows x 64B each (XOR-swizzled, no padding).
// swizzled chunk: byte(r, g) = r*64 + ((g ^ ((r>>1)&3)) << 4)
#define TILE_B 8192
#define STAGE_B 32768
#define NSTAGE 3
#define SM_TOT (NSTAGE * STAGE_B)

// D[M,N] = epi(scale * A[M,K] @ B[N,K]^T), interleaved-split bf16, HMMA.
// CTA 128x128, BK=32, 256 thr = 8 warps (2M x 4N), warp 64x32, 3-stage cp.async.
__global__ void __launch_bounds__(256, 2) gemm_sp(
    const __nv_bfloat16* __restrict__ A, const __nv_bfloat16* __restrict__ B,
    float* __restrict__ C, __nv_bfloat16* __restrict__ O,
    int K, int lda, int ldb, int ldc,
    long sA, long sB, long sC,
    const float* __restrict__ bias, const float* __restrict__ residual,
    float scale, int act, int pe)
{
    extern __shared__ char sm[];
    uint32_t sb = smem_u32(sm);

    int tid = threadIdx.x, wid = tid >> 5, lane = tid & 31;
    long bz = blockIdx.z;
    const char* Ab = (const char*)(A + bz * 2 * sA);
    const char* Bb = (const char*)(B + bz * 2 * sB);
    if (C) C += bz * sC;
    if (O) O += bz * 2 * sC;
    const float* res = residual ? residual + bz * sC : nullptr;
    long row0 = (long)blockIdx.y * 128, col0 = (long)blockIdx.x * 128;

    int wm = wid >> 2, wn = wid & 3;
    int m0w = wm * 64, n0w = wn * 32;

    float acc[4][4][4];
#pragma unroll
    for (int i = 0; i < 4; i++)
#pragma unroll
        for (int j = 0; j < 4; j++)
#pragma unroll
            for (int e = 0; e < 4; e++) acc[i][j][e] = 0.f;

    // loader: row = tid>>1, handles groups sg, sg+1 (16B each of hi and lo)
    const int r_ld = tid >> 1;
    const int sg = (tid & 1) * 2;
    const int NC = K >> 5;

    const char* a_src = Ab + (row0 + r_ld) * (4L * lda) + sg * 32;
    const char* b_src = Bb + (col0 + r_ld) * (4L * ldb) + sg * 32;
    const int ch0 = (sg ^ ((r_ld >> 1) & 3)) << 4;
    const int ch1 = ch0 ^ 16;
    const uint32_t stA = sb + r_ld * 64;
    const uint32_t stB = stA + 2 * TILE_B;

    auto issue = [&](int c, uint32_t bofs) {
        const char* sa = a_src + (long)c * 128;
        const char* sbp = b_src + (long)c * 128;
        uint32_t dA = stA + bofs;
        uint32_t dB = stB + bofs;
        CP16(dA + ch0, sa);                      // hi g(sg)
        CP16(dA + ch1, sa + 32);                 // hi g(sg+1)
        CP16(dA + TILE_B + ch0, sa + 16);        // lo g(sg)
        CP16(dA + TILE_B + ch1, sa + 48);        // lo g(sg+1)
        CP16(dB + ch0, sbp);
        CP16(dB + ch1, sbp + 32);
        CP16(dB + TILE_B + ch0, sbp + 16);
        CP16(dB + TILE_B + ch1, sbp + 48);
    };

    // ldmatrix addresses (stage 0, ks=0; stage: +bofs, ks=1: XOR 32)
    uint32_t a_addr_h[4], a_addr_l[4], b_addr_h[2], b_addr_l[2];
#pragma unroll
    for (int i = 0; i < 4; i++) {
        uint32_t r = m0w + i * 16 + (lane & 15);
        uint32_t g0 = lane >> 4;
        uint32_t byt = r * 64 + ((g0 ^ ((r >> 1) & 3)) << 4);
        a_addr_h[i] = sb + byt;
        a_addr_l[i] = sb + TILE_B + byt;
    }
#pragma unroll
    for (int jp = 0; jp < 2; jp++) {
        uint32_t r = n0w + jp * 16 + ((lane >> 4) << 3) + (lane & 7);
        uint32_t g0 = (lane >> 3) & 1;
        uint32_t byt = r * 64 + ((g0 ^ ((r >> 1) & 3)) << 4);
        b_addr_h[jp] = sb + 2 * TILE_B + byt;
        b_addr_l[jp] = sb + 3 * TILE_B + byt;
    }

    issue(0, 0); CP_COMMIT();
    issue(1, STAGE_B); CP_COMMIT();

    int sidx = 0, sidx2 = 2;   // stage of chunk c, stage of chunk c+2
    for (int c = 0; c < NC; c++) {
        CP_WAIT1();
        __syncthreads();
        if (c + 2 < NC) issue(c + 2, sidx2 * STAGE_B);
        CP_COMMIT();

        uint32_t bofs = sidx * STAGE_B;
#pragma unroll
        for (int ks = 0; ks < 2; ks++) {
            uint32_t kx = ks * 32;
            uint32_t ah[4][4], al[4][4], bh[2][4], bl[2][4];
#pragma unroll
            for (int i = 0; i < 4; i++) {
                ldsm4(ah[i], (a_addr_h[i] + bofs) ^ kx);
                ldsm4(al[i], (a_addr_l[i] + bofs) ^ kx);
            }
#pragma unroll
            for (int jp = 0; jp < 2; jp++) {
                ldsm4(bh[jp], (b_addr_h[jp] + bofs) ^ kx);
                ldsm4(bl[jp], (b_addr_l[jp] + bofs) ^ kx);
            }
#pragma unroll
            for (int i = 0; i < 4; i++)
#pragma unroll
                for (int j = 0; j < 4; j++)
                    mma16816(acc[i][j], ah[i], &bh[j >> 1][(j & 1) * 2]);
#pragma unroll
            for (int i = 0; i < 4; i++)
#pragma unroll
                for (int j = 0; j < 4; j++)
                    mma16816(acc[i][j], ah[i], &bl[j >> 1][(j & 1) * 2]);
#pragma unroll
            for (int i = 0; i < 4; i++)
#pragma unroll
                for (int j = 0; j < 4; j++)
                    mma16816(acc[i][j], al[i], &bh[j >> 1][(j & 1) * 2]);
        }
        sidx = (sidx == 2) ? 0 : sidx + 1;
        sidx2 = (sidx2 == 2) ? 0 : sidx2 + 1;
    }
    CP_WAIT0();

    // epilogue: thread holds C[r1][cc..cc+1], C[r1+8][cc..cc+1] per (i,j)
#pragma unroll
    for (int i = 0; i < 4; i++) {
        long r1 = row0 + m0w + i * 16 + (lane >> 2);
        long r2 = r1 + 8;
#pragma unroll
        for (int j = 0; j < 4; j++) {
            long cc = col0 + n0w + j * 8 + 2 * (lane & 3);
            float2 bi = bias ? *(const float2*)(bias + cc) : make_float2(0.f, 0.f);
            float v0 = acc[i][j][0] * scale + bi.x;
            float v1 = acc[i][j][1] * scale + bi.y;
            float v2 = acc[i][j][2] * scale + bi.x;
            float v3 = acc[i][j][3] * scale + bi.y;
            if (act) { v0 = gelu_f(v0); v1 = gelu_f(v1); v2 = gelu_f(v2); v3 = gelu_f(v3); }
            if (res) {
                float2 q1 = *(const float2*)(res + r1 * ldc + cc);
                float2 q2 = *(const float2*)(res + r2 * ldc + cc);
                v0 += q1.x; v1 += q1.y; v2 += q2.x; v3 += q2.y;
            }
            if (pe) {
                float d0 = expf((float)cc * (-2.0f / 1024.0f) * 6.9077552789821370521f);
                float d1 = expf((float)(cc + 1) * (-2.0f / 1024.0f) * 6.9077552789821370521f);
                int s1 = (int)(r1 & (S_LEN - 1)), s2 = (int)(r2 & (S_LEN - 1));
                float a10 = s1 * d0, a11 = s1 * d1, a20 = s2 * d0, a21 = s2 * d1;
                v0 += (s1 & 1) ? cosf(a10) : sinf(a10);
                v1 += (s1 & 1) ? cosf(a11) : sinf(a11);
                v2 += (s2 & 1) ? cosf(a20) : sinf(a20);
                v3 += (s2 & 1) ? cosf(a21) : sinf(a21);
            }
            if (C) {
                *(float2*)(C + r1 * ldc + cc) = make_float2(v0, v1);
                *(float2*)(C + r2 * ldc + cc) = make_float2(v2, v3);
            }
            if (O) {
                uint32_t h, l;
                long i1 = il_idx(r1, (int)cc, ldc), i2 = il_idx(r2, (int)cc, ldc);
                split2(v0, v1, h, l);
                *(uint32_t*)(O + i1) = h;
                *(uint32_t*)(O + i1 + 8) = l;
                split2(v2, v3, h, l);
                *(uint32_t*)(O + i2) = h;
                *(uint32_t*)(O + i2 + 8) = l;
            }
        }
    }
}

// fp32 [R,1024] -> interleaved split, grid-stride over float4s
__global__ void split_kernel(const float* __restrict__ src,
                             __nv_bfloat16* __restrict__ dst, long n4)
{
    long i = (long)blockIdx.x * blockDim.x + threadIdx.x;
    long stride = (long)gridDim.x * blockDim.x;
    for (; i < n4; i += stride) {
        float4 f = ((const float4*)src)[i];
        uint2 h, l;
        split4(f, h, l);
        long r = i >> 8;              // 256 float4 per row (K=1024)
        int k0 = (int)(i & 255) * 4;
        long o = il_idx(r, k0, 1024);
        *(uint2*)(dst + o) = h;
        *(uint2*)(dst + o + 8) = l;
    }
}

// vt[b][c][s] = qkv[b,s,2C+c], interleaved form both sides
__global__ void transpose_v_bf(const __nv_bfloat16* __restrict__ q_il,
                               __nv_bfloat16* __restrict__ v_il)
{
    __shared__ __nv_bfloat16 th[32][34], tl[32][34];
    int b = blockIdx.z;
    int s0 = blockIdx.x * 32, c0 = blockIdx.y * 32;
    int tx = threadIdx.x, ty = threadIdx.y;
    const __nv_bfloat16* src = q_il + (long)b * S_LEN * 2 * 3 * C_DIM;
#pragma unroll
    for (int i = 0; i < 32; i += 8) {
        long o = il_idx((long)(s0 + ty + i), 2 * C_DIM + c0 + tx, 3 * C_DIM);
        th[ty + i][tx] = src[o];
        tl[ty + i][tx] = src[o + 8];
    }
    __syncthreads();
    __nv_bfloat16* dst = v_il + (long)b * C_DIM * 2 * S_LEN;
#pragma unroll
    for (int i = 0; i < 32; i += 8) {
        long o = il_idx((long)(c0 + ty + i), s0 + tx, S_LEN);
        dst[o] = th[tx][ty + i];
        dst[o + 8] = tl[tx][ty + i];
    }
}

// layernorm over last dim (1024), fp32 in -> interleaved split out
__global__ void layernorm_kernel(const float* __restrict__ h,
                                 const float* __restrict__ g,
                                 const float* __restrict__ b,
                                 __nv_bfloat16* __restrict__ o_il)
{
    __shared__ float sa[8], sb2[8];
    long row = blockIdx.x;
    const float* p = h + row * C_DIM;
    int tid = threadIdx.x;
    float v[4];
    float s1 = 0.f, s2 = 0.f;
#pragma unroll
    for (int i = 0; i < 4; i++) {
        v[i] = p[tid + i * 256];
        s1 += v[i];
        s2 += v[i] * v[i];
    }
#pragma unroll
    for (int o = 16; o > 0; o >>= 1) {
        s1 += __shfl_down_sync(0xffffffffu, s1, o);
        s2 += __shfl_down_sync(0xffffffffu, s2, o);
    }
    int lane = tid & 31, w = tid >> 5;
    if (lane == 0) { sa[w] = s1; sb2[w] = s2; }
    __syncthreads();
    if (tid < 32) {
        s1 = (tid < 8) ? sa[tid] : 0.f;
        s2 = (tid < 8) ? sb2[tid] : 0.f;
#pragma unroll
        for (int o = 4; o > 0; o >>= 1) {
            s1 += __shfl_down_sync(0xffffffffu, s1, o);
            s2 += __shfl_down_sync(0xffffffffu, s2, o);
        }
        if (tid == 0) { sa[0] = s1; sb2[0] = s2; }
    }
    __syncthreads();
    float mu = sa[0] * (1.0f / 1024.0f);
    float var = sb2[0] * (1.0f / 1024.0f) - mu * mu;
    float inv = rsqrtf(var + 1e-5f);
#pragma unroll
    for (int i = 0; i < 4; i++) {
        int c = tid + i * 256;
        float y = (v[i] - mu) * inv * g[c] + b[c];
        __nv_bfloat16 hb = __float2bfloat16_rn(y);
        long o = il_idx(row, c, C_DIM);
        o_il[o] = hb;
        o_il[o + 8] = __float2bfloat16_rn(y - __bfloat162float(hb));
    }
}

// softmax over last dim (1024), fp32 in -> interleaved split out
__global__ void softmax_kernel(const float* __restrict__ att,
                               __nv_bfloat16* __restrict__ o_il)
{
    __shared__ float sh[8];
    long row = blockIdx.x;
    const float* p = att + row * C_DIM;
    int tid = threadIdx.x;
    float v[4];
    float m = -INFINITY;
#pragma unroll
    for (int i = 0; i < 4; i++) {
        v[i] = p[tid + i * 256];
        m = fmaxf(m, v[i]);
    }
#pragma unroll
    for (int o = 16; o > 0; o >>= 1)
        m = fmaxf(m, __shfl_down_sync(0xffffffffu, m, o));
    int lane = tid & 31, w = tid >> 5;
    if (lane == 0) sh[w] = m;
    __syncthreads();
    if (tid < 32) {
        m = (tid < 8) ? sh[tid] : -INFINITY;
#pragma unroll
        for (int o = 4; o > 0; o >>= 1)
            m = fmaxf(m, __shfl_down_sync(0xffffffffu, m, o));
        if (tid == 0) sh[0] = m;
    }
    __syncthreads();
    m = sh[0];
    __syncthreads();
    float e[4];
    float s = 0.f;
#pragma unroll
    for (int i = 0; i < 4; i++) {
        e[i] = expf(v[i] - m);
        s += e[i];
    }
#pragma unroll
    for (int o = 16; o > 0; o >>= 1)
        s += __shfl_down_sync(0xffffffffu, s, o);
    if (lane == 0) sh[w] = s;
    __syncthreads();
    if (tid < 32) {
        s = (tid < 8) ? sh[tid] : 0.f;
#pragma unroll
        for (int o = 4; o > 0; o >>= 1)
            s += __shfl_down_sync(0xffffffffu, s, o);
        if (tid == 0) sh[0] = s;
    }
    __syncthreads();
    float inv = 1.0f / sh[0];
#pragma unroll
    for (int i = 0; i < 4; i++) {
        int c = tid + i * 256;
        float y = e[i] * inv;
        __nv_bfloat16 hb = __float2bfloat16_rn(y);
        long o = il_idx(row, c, C_DIM);
        o_il[o] = hb;
        o_il[o + 8] = __float2bfloat16_rn(y - __bfloat162float(hb));
    }
}

static void launch_gemm(const __nv_bfloat16* A, const __nv_bfloat16* B,
                        float* C, __nv_bfloat16* O,
                        int M, int N, int K, int lda, int ldb, int ldc,
                        long sA, long sB, long sC, int batches,
                        const float* bias, const float* residual,
                        float scale, int act, int pe)
{
    dim3 grid(N / 128, M / 128, batches);
    gemm_sp<<<grid, 256, SM_TOT>>>(A, B, C, O, K, lda, ldb, ldc,
                                   sA, sB, sC, bias, residual, scale, act, pe);
}

extern "C" void kernel_launch(void* const* d_in, const int* in_sizes, int n_in,
                              void* d_out, int out_size)
{
    const float* x        = (const float*)d_in[0];
    const float* fc_in_w  = (const float*)d_in[1];
    const float* fc_in_b  = (const float*)d_in[2];
    const float* ln_g     = (const float*)d_in[3];
    const float* ln_b     = (const float*)d_in[4];
    const float* qkv_w    = (const float*)d_in[5];
    const float* qkv_b    = (const float*)d_in[6];
    const float* proj_w   = (const float*)d_in[7];
    const float* proj_b   = (const float*)d_in[8];
    const float* fc_out_w = (const float*)d_in[9];
    const float* fc_out_b = (const float*)d_in[10];
    float* out = (float*)d_out;

    cudaFuncSetAttribute(gemm_sp, cudaFuncAttributeMaxDynamicSharedMemorySize, SM_TOT);

    __nv_bfloat16 *wil, *xil, *ail, *qil, *vil, *scil, *smil;
    float *h0, *att, *pred;
    cudaGetSymbolAddress((void**)&wil, g_w_il);
    cudaGetSymbolAddress((void**)&xil, g_x_il);
    cudaGetSymbolAddress((void**)&ail, g_a_il);
    cudaGetSymbolAddress((void**)&qil, g_qkv_il);
    cudaGetSymbolAddress((void**)&vil, g_vt_il);
    cudaGetSymbolAddress((void**)&scil, g_sc_il);
    cudaGetSymbolAddress((void**)&smil, g_sm_il);
    cudaGetSymbolAddress((void**)&h0, g_h0);
    cudaGetSymbolAddress((void**)&att, g_att);
    cudaGetSymbolAddress((void**)&pred, g_pred);

    // split inputs/weights (all have K=1024 per row)
    split_kernel<<<512, 256>>>(x, xil, (long)M_TOT * C_DIM / 4);
    split_kernel<<<256, 256>>>(fc_in_w, wil + W_FCIN, (long)C_DIM * C_DIM / 4);
    split_kernel<<<1024, 256>>>(qkv_w, wil + W_QKV, (long)4 * 3 * C_DIM * C_DIM / 4);
    split_kernel<<<512, 256>>>(proj_w, wil + W_PROJ, (long)4 * C_DIM * C_DIM / 4);
    split_kernel<<<256, 256>>>(fc_out_w, wil + W_FCOUT, (long)C_DIM * C_DIM / 4);

    // h0 = x @ fc_in_w^T + fc_in_b    (fp32 out only)
    launch_gemm(xil, wil + W_FCIN, h0, nullptr,
                M_TOT, C_DIM, C_DIM, C_DIM, C_DIM, C_DIM, 0, 0, 0, 1,
                fc_in_b, nullptr, 1.0f, 0, 0);

    // a = split(layernorm(h0))
    layernorm_kernel<<<M_TOT, 256>>>(h0, ln_g, ln_b, ail);

    for (int i = 0; i < 4; i++) {
        long wq = W_QKV + 2L * i * 3 * C_DIM * C_DIM;
        long wp = W_PROJ + 2L * i * C_DIM * C_DIM;

        // qkv = split(gelu(a @ qkv_w[i]^T + qkv_b[i]))
        launch_gemm(ail, wil + wq, nullptr, qil,
                    M_TOT, 3 * C_DIM, C_DIM, C_DIM, C_DIM, 3 * C_DIM, 0, 0, 0, 1,
                    qkv_b + (long)i * 3 * C_DIM, nullptr, 1.0f, 1, 0);

        // vt = transpose of v (interleaved)
        transpose_v_bf<<<dim3(S_LEN / 32, C_DIM / 32, NB), dim3(32, 8)>>>(qil, vil);

        // scores = split(q @ k^T / C)  (batched; k-part = +2048 il elems)
        launch_gemm(qil, qil + 2048, nullptr, scil,
                    S_LEN, S_LEN, C_DIM, 3 * C_DIM, 3 * C_DIM, S_LEN,
                    (long)S_LEN * 3 * C_DIM, (long)S_LEN * 3 * C_DIM, (long)S_LEN * S_LEN,
                    NB, nullptr, nullptr, 1.0f / 1024.0f, 0, 0);

        // att = scores @ vt^T   (fp32 out, batched)
        launch_gemm(scil, vil, att, nullptr,
                    S_LEN, C_DIM, S_LEN, S_LEN, S_LEN, C_DIM,
                    (long)S_LEN * S_LEN, (long)C_DIM * S_LEN, (long)S_LEN * C_DIM,
                    NB, nullptr, nullptr, 1.0f, 0, 0);

        // sm = split(softmax(att))
        softmax_kernel<<<M_TOT, 256>>>(att, smil);

        // a = split(gelu(sm @ proj_w[i]^T + proj_b[i]) [+ pred]); fp32 pred copy on i==0
        launch_gemm(smil, wil + wp, (i == 0) ? pred : nullptr, ail,
                    M_TOT, C_DIM, C_DIM, C_DIM, C_DIM, C_DIM, 0, 0, 0, 1,
                    proj_b + (long)i * C_DIM, (i == 0) ? nullptr : pred, 1.0f, 1, 0);
    }

    // out = a @ fc_out_w^T + fc_out_b + pose_enc
    launch_gemm(ail, wil + W_FCOUT, out, nullptr,
                M_TOT, C_DIM, C_DIM, C_DIM, C_DIM, C_DIM, 0, 0, 0, 1,
                fc_out_b, nullptr, 1.0f, 0, 1);
}

// round 8
// speedup vs baseline: 1.4040x; 1.2860x over previous
#include <cuda_runtime.h>
#include <cuda_bf16.h>
#include <math.h>
#include <stdint.h>

#define M_TOT 8192
#define C_DIM 1024
#define S_LEN 2048
#define NB 4

// ---------------- static scratch (no allocations allowed) ----------------
// fp32
__device__ float g_h0[M_TOT * C_DIM];
__device__ float g_att[M_TOT * C_DIM];
__device__ float g_pred[M_TOT * C_DIM];
// bf16 hi/lo split buffers (separate arrays, element offsets)
#define W_FCIN 0
#define W_QKV  1048576
#define W_PROJ 13631488
#define W_FCOUT 17825792
#define W_TOTAL 18874368
__device__ __nv_bfloat16 g_w_hi[W_TOTAL];
__device__ __nv_bfloat16 g_w_lo[W_TOTAL];
__device__ __nv_bfloat16 g_x_hi[M_TOT * C_DIM];
__device__ __nv_bfloat16 g_x_lo[M_TOT * C_DIM];
__device__ __nv_bfloat16 g_a_hi[M_TOT * C_DIM];
__device__ __nv_bfloat16 g_a_lo[M_TOT * C_DIM];
__device__ __nv_bfloat16 g_qkv_hi[(long)M_TOT * 3 * C_DIM];
__device__ __nv_bfloat16 g_qkv_lo[(long)M_TOT * 3 * C_DIM];
__device__ __nv_bfloat16 g_vt_hi[(long)NB * C_DIM * S_LEN];
__device__ __nv_bfloat16 g_vt_lo[(long)NB * C_DIM * S_LEN];
__device__ __nv_bfloat16 g_sc_hi[(long)NB * S_LEN * S_LEN];
__device__ __nv_bfloat16 g_sc_lo[(long)NB * S_LEN * S_LEN];
__device__ __nv_bfloat16 g_sm_hi[M_TOT * C_DIM];
__device__ __nv_bfloat16 g_sm_lo[M_TOT * C_DIM];

// ---------------- helpers ----------------
__device__ __forceinline__ uint32_t smem_u32(const void* p) {
    uint32_t a;
    asm("{ .reg .u64 t; cvta.to.shared.u64 t, %1; cvt.u32.u64 %0, t; }" : "=r"(a) : "l"(p));
    return a;
}
__device__ __forceinline__ float gelu_f(float x) {
    return 0.5f * x * (1.0f + erff(x * 0.70710678118654752f));
}
__device__ __forceinline__ uint32_t bf2_bits(__nv_bfloat162 v) {
    return *reinterpret_cast<uint32_t*>(&v);
}
__device__ __forceinline__ void split4(float4 f, uint2& hi, uint2& lo) {
    __nv_bfloat162 h01 = __floats2bfloat162_rn(f.x, f.y);
    __nv_bfloat162 h23 = __floats2bfloat162_rn(f.z, f.w);
    float2 g01 = __bfloat1622float2(h01), g23 = __bfloat1622float2(h23);
    __nv_bfloat162 l01 = __floats2bfloat162_rn(f.x - g01.x, f.y - g01.y);
    __nv_bfloat162 l23 = __floats2bfloat162_rn(f.z - g23.x, f.w - g23.y);
    hi = make_uint2(bf2_bits(h01), bf2_bits(h23));
    lo = make_uint2(bf2_bits(l01), bf2_bits(l23));
}
__device__ __forceinline__ void split2(float a, float b, uint32_t& hi, uint32_t& lo) {
    __nv_bfloat162 h = __floats2bfloat162_rn(a, b);
    float2 g = __bfloat1622float2(h);
    __nv_bfloat162 l = __floats2bfloat162_rn(a - g.x, b - g.y);
    hi = bf2_bits(h); lo = bf2_bits(l);
}
__device__ __forceinline__ void ldsm4(uint32_t* r, uint32_t addr) {
    asm volatile("ldmatrix.sync.aligned.m8n8.x4.shared.b16 {%0,%1,%2,%3}, [%4];"
        : "=r"(r[0]), "=r"(r[1]), "=r"(r[2]), "=r"(r[3]) : "r"(addr));
}
__device__ __forceinline__ void ldsm2(uint32_t* r, uint32_t addr) {
    asm volatile("ldmatrix.sync.aligned.m8n8.x2.shared.b16 {%0,%1}, [%2];"
        : "=r"(r[0]), "=r"(r[1]) : "r"(addr));
}
__device__ __forceinline__ void mma16816(float* d, const uint32_t* a, const uint32_t* b) {
    asm volatile("mma.sync.aligned.m16n8k16.row.col.f32.bf16.bf16.f32 "
        "{%0,%1,%2,%3}, {%4,%5,%6,%7}, {%8,%9}, {%0,%1,%2,%3};"
        : "+f"(d[0]), "+f"(d[1]), "+f"(d[2]), "+f"(d[3])
        : "r"(a[0]), "r"(a[1]), "r"(a[2]), "r"(a[3]), "r"(b[0]), "r"(b[1]));
}
#define CP16(dst, src) \
    asm volatile("cp.async.ca.shared.global [%0], [%1], 16;" :: "r"(dst), "l"(src) : "memory")
#define CP_COMMIT() asm volatile("cp.async.commit_group;" ::: "memory")
#define CP_WAIT1() asm volatile("cp.async.wait_group 1;" ::: "memory")

// SMEM stage: AH/AL 128 rows x 32 bf16 (80B row), BH/BL 256 rows x 32 bf16 (80B row)
#define ROW_B 80
#define A_TILE_B 10240
#define B_TILE_B 20480
#define OFF_AH 0
#define OFF_AL 10240
#define OFF_BH 20480
#define OFF_BL 40960
#define STAGE_B 61440
#define SM_TOT (2 * STAGE_B)

// D[M,N] = epi(scale * A[M,K] @ B[N,K]^T), pre-split bf16, HMMA, 2-stage cp.async.
// CTA tile 128x256, BK=32, 512 threads = 16 warps (2M x 8N), warp tile 64x32.
__global__ void __launch_bounds__(512, 1) gemm_sp(
    const __nv_bfloat16* __restrict__ Ahi, const __nv_bfloat16* __restrict__ Alo,
    const __nv_bfloat16* __restrict__ Bhi, const __nv_bfloat16* __restrict__ Blo,
    float* __restrict__ C, __nv_bfloat16* __restrict__ Ohi, __nv_bfloat16* __restrict__ Olo,
    int K, int lda, int ldb, int ldc,
    long sA, long sB, long sC,
    const float* __restrict__ bias, const float* __restrict__ residual,
    float scale, int act, int pe)
{
    extern __shared__ char sm[];
    uint32_t sb = smem_u32(sm);

    int tid = threadIdx.x, wid = tid >> 5, lane = tid & 31;
    long bz = blockIdx.z;
    Ahi += bz * sA; Alo += bz * sA; Bhi += bz * sB; Blo += bz * sB;
    if (C) C += bz * sC;
    if (Ohi) { Ohi += bz * sC; Olo += bz * sC; }
    const float* res = residual ? residual + bz * sC : nullptr;
    long row0 = (long)blockIdx.y * 128, col0 = (long)blockIdx.x * 256;

    int wm = wid >> 3, wn = wid & 7;     // 2 x 8 warp grid
    int m0w = wm * 64, n0w = wn * 32;

    float acc[4][4][4];
#pragma unroll
    for (int i = 0; i < 4; i++)
#pragma unroll
        for (int j = 0; j < 4; j++)
#pragma unroll
            for (int e = 0; e < 4; e++) acc[i][j][e] = 0.f;

    // A loader: row rA = tid>>2 (0..127), 16B quarter qA = tid&3 ; 1 CP16 per buf
    // B loader: row rB = tid>>1 (0..255), half sgB = (tid&1)*2 ; 2 CP16 per buf
    const int rA = tid >> 2, qA = tid & 3;
    const int rB = tid >> 1, sgB = (tid & 1) * 2;
    const int NC = K >> 5;

    const __nv_bfloat16* a_hi_src = Ahi + (row0 + rA) * lda + qA * 8;
    const __nv_bfloat16* a_lo_src = Alo + (row0 + rA) * lda + qA * 8;
    const __nv_bfloat16* b_hi_src = Bhi + (col0 + rB) * ldb + sgB * 8;
    const __nv_bfloat16* b_lo_src = Blo + (col0 + rB) * ldb + sgB * 8;
    const uint32_t stA = sb + rA * ROW_B + qA * 16;
    const uint32_t stB = sb + rB * ROW_B + sgB * 16;

    auto issue = [&](int c, uint32_t bofs) {
        long ko = (long)c * 32;
        CP16(stA + OFF_AH + bofs, a_hi_src + ko);
        CP16(stA + OFF_AL + bofs, a_lo_src + ko);
        CP16(stB + OFF_BH + bofs,      b_hi_src + ko);
        CP16(stB + OFF_BH + bofs + 16, b_hi_src + ko + 8);
        CP16(stB + OFF_BL + bofs,      b_lo_src + ko);
        CP16(stB + OFF_BL + bofs + 16, b_lo_src + ko + 8);
    };

    // ldmatrix addresses (stage 0 base; add bofs, + ks*32 per k16 step)
    uint32_t a_addr_h[4], a_addr_l[4], b_addr_h[4], b_addr_l[4];
#pragma unroll
    for (int i = 0; i < 4; i++) {
        uint32_t r = m0w + i * 16 + (lane & 15);
        uint32_t byt = r * ROW_B + (lane >> 4) * 16;
        a_addr_h[i] = sb + OFF_AH + byt;
        a_addr_l[i] = sb + OFF_AL + byt;
    }
#pragma unroll
    for (int j = 0; j < 4; j++) {
        uint32_t r = n0w + j * 8 + (lane & 7);
        uint32_t byt = r * ROW_B + ((lane >> 3) & 1) * 16;
        b_addr_h[j] = sb + OFF_BH + byt;
        b_addr_l[j] = sb + OFF_BL + byt;
    }

    issue(0, 0); CP_COMMIT();
    if (NC > 1) issue(1, STAGE_B);
    CP_COMMIT();

    for (int c = 0; c < NC; c++) {
        CP_WAIT1();
        __syncthreads();
        uint32_t bofs = (c & 1) * STAGE_B;
#pragma unroll
        for (int ks = 0; ks < 2; ks++) {
            uint32_t ah[4][4], al[4][4], bh[4][2], bl[4][2];
#pragma unroll
            for (int i = 0; i < 4; i++) {
                ldsm4(ah[i], a_addr_h[i] + bofs + ks * 32);
                ldsm4(al[i], a_addr_l[i] + bofs + ks * 32);
            }
#pragma unroll
            for (int j = 0; j < 4; j++) {
                ldsm2(bh[j], b_addr_h[j] + bofs + ks * 32);
                ldsm2(bl[j], b_addr_l[j] + bofs + ks * 32);
            }
#pragma unroll
            for (int i = 0; i < 4; i++)
#pragma unroll
                for (int j = 0; j < 4; j++) mma16816(acc[i][j], ah[i], bh[j]);
#pragma unroll
            for (int i = 0; i < 4; i++)
#pragma unroll
                for (int j = 0; j < 4; j++) mma16816(acc[i][j], ah[i], bl[j]);
#pragma unroll
            for (int i = 0; i < 4; i++)
#pragma unroll
                for (int j = 0; j < 4; j++) mma16816(acc[i][j], al[i], bh[j]);
        }
        __syncthreads();
        if (c + 2 < NC) issue(c + 2, (c & 1) * STAGE_B);
        CP_COMMIT();
    }

    // epilogue: thread holds C[r1][cc..cc+1], C[r1+8][cc..cc+1] per (i,j)
#pragma unroll
    for (int i = 0; i < 4; i++) {
        long r1 = row0 + m0w + i * 16 + (lane >> 2);
        long r2 = r1 + 8;
#pragma unroll
        for (int j = 0; j < 4; j++) {
            long cc = col0 + n0w + j * 8 + 2 * (lane & 3);
            float2 bi = bias ? *(const float2*)(bias + cc) : make_float2(0.f, 0.f);
            float v0 = acc[i][j][0] * scale + bi.x;
            float v1 = acc[i][j][1] * scale + bi.y;
            float v2 = acc[i][j][2] * scale + bi.x;
            float v3 = acc[i][j][3] * scale + bi.y;
            if (act) { v0 = gelu_f(v0); v1 = gelu_f(v1); v2 = gelu_f(v2); v3 = gelu_f(v3); }
            if (res) {
                float2 q1 = *(const float2*)(res + r1 * ldc + cc);
                float2 q2 = *(const float2*)(res + r2 * ldc + cc);
                v0 += q1.x; v1 += q1.y; v2 += q2.x; v3 += q2.y;
            }
            if (pe) {
                float d0 = expf((float)cc * (-2.0f / 1024.0f) * 6.9077552789821370521f);
                float d1 = expf((float)(cc + 1) * (-2.0f / 1024.0f) * 6.9077552789821370521f);
                int s1 = (int)(r1 & (S_LEN - 1)), s2 = (int)(r2 & (S_LEN - 1));
                float a10 = s1 * d0, a11 = s1 * d1, a20 = s2 * d0, a21 = s2 * d1;
                v0 += (s1 & 1) ? cosf(a10) : sinf(a10);
                v1 += (s1 & 1) ? cosf(a11) : sinf(a11);
                v2 += (s2 & 1) ? cosf(a20) : sinf(a20);
                v3 += (s2 & 1) ? cosf(a21) : sinf(a21);
            }
            if (C) {
                *(float2*)(C + r1 * ldc + cc) = make_float2(v0, v1);
                *(float2*)(C + r2 * ldc + cc) = make_float2(v2, v3);
            }
            if (Ohi) {
                uint32_t h, l;
                split2(v0, v1, h, l);
                *(uint32_t*)(Ohi + r1 * ldc + cc) = h;
                *(uint32_t*)(Olo + r1 * ldc + cc) = l;
                split2(v2, v3, h, l);
                *(uint32_t*)(Ohi + r2 * ldc + cc) = h;
                *(uint32_t*)(Olo + r2 * ldc + cc) = l;
            }
        }
    }
}

// fp32 -> bf16 hi/lo split, grid-stride over float4s
__global__ void split_kernel(const float* __restrict__ src,
                             __nv_bfloat16* __restrict__ hi,
                             __nv_bfloat16* __restrict__ lo, long n4)
{
    long i = (long)blockIdx.x * blockDim.x + threadIdx.x;
    long stride = (long)gridDim.x * blockDim.x;
    for (; i < n4; i += stride) {
        float4 f = ((const float4*)src)[i];
        uint2 h, l;
        split4(f, h, l);
        ((uint2*)hi)[i] = h;
        ((uint2*)lo)[i] = l;
    }
}

// vt[b][c][s] = qkv[b,s,2C+c], split form
__global__ void transpose_v_bf(const __nv_bfloat16* __restrict__ qh,
                               const __nv_bfloat16* __restrict__ ql,
                               __nv_bfloat16* __restrict__ vh,
                               __nv_bfloat16* __restrict__ vl)
{
    __shared__ __nv_bfloat16 th[32][34], tl[32][34];
    int b = blockIdx.z;
    int s0 = blockIdx.x * 32, c0 = blockIdx.y * 32;
    int tx = threadIdx.x, ty = threadIdx.y;
    const __nv_bfloat16* sh = qh + (long)b * S_LEN * 3 * C_DIM + 2 * C_DIM;
    const __nv_bfloat16* sl = ql + (long)b * S_LEN * 3 * C_DIM + 2 * C_DIM;
#pragma unroll
    for (int i = 0; i < 32; i += 8) {
        long o = (long)(s0 + ty + i) * (3 * C_DIM) + c0 + tx;
        th[ty + i][tx] = sh[o];
        tl[ty + i][tx] = sl[o];
    }
    __syncthreads();
    __nv_bfloat16* dh = vh + (long)b * C_DIM * S_LEN;
    __nv_bfloat16* dl = vl + (long)b * C_DIM * S_LEN;
#pragma unroll
    for (int i = 0; i < 32; i += 8) {
        long o = (long)(c0 + ty + i) * S_LEN + s0 + tx;
        dh[o] = th[tx][ty + i];
        dl[o] = tl[tx][ty + i];
    }
}

// layernorm over last dim (1024), fp32 in -> split bf16 out
__global__ void layernorm_kernel(const float* __restrict__ h,
                                 const float* __restrict__ g,
                                 const float* __restrict__ b,
                                 __nv_bfloat16* __restrict__ ohi,
                                 __nv_bfloat16* __restrict__ olo)
{
    __shared__ float sa[8], sb2[8];
    long row = blockIdx.x;
    const float* p = h + row * C_DIM;
    int tid = threadIdx.x;
    float v[4];
    float s1 = 0.f, s2 = 0.f;
#pragma unroll
    for (int i = 0; i < 4; i++) {
        v[i] = p[tid + i * 256];
        s1 += v[i];
        s2 += v[i] * v[i];
    }
#pragma unroll
    for (int o = 16; o > 0; o >>= 1) {
        s1 += __shfl_down_sync(0xffffffffu, s1, o);
        s2 += __shfl_down_sync(0xffffffffu, s2, o);
    }
    int lane = tid & 31, w = tid >> 5;
    if (lane == 0) { sa[w] = s1; sb2[w] = s2; }
    __syncthreads();
    if (tid < 32) {
        s1 = (tid < 8) ? sa[tid] : 0.f;
        s2 = (tid < 8) ? sb2[tid] : 0.f;
#pragma unroll
        for (int o = 4; o > 0; o >>= 1) {
            s1 += __shfl_down_sync(0xffffffffu, s1, o);
            s2 += __shfl_down_sync(0xffffffffu, s2, o);
        }
        if (tid == 0) { sa[0] = s1; sb2[0] = s2; }
    }
    __syncthreads();
    float mu = sa[0] * (1.0f / 1024.0f);
    float var = sb2[0] * (1.0f / 1024.0f) - mu * mu;
    float inv = rsqrtf(var + 1e-5f);
#pragma unroll
    for (int i = 0; i < 4; i++) {
        int c = tid + i * 256;
        float y = (v[i] - mu) * inv * g[c] + b[c];
        __nv_bfloat16 hb = __float2bfloat16_rn(y);
        ohi[row * C_DIM + c] = hb;
        olo[row * C_DIM + c] = __float2bfloat16_rn(y - __bfloat162float(hb));
    }
}

// softmax over last dim (1024), fp32 in -> split bf16 out
__global__ void softmax_kernel(const float* __restrict__ att,
                               __nv_bfloat16* __restrict__ ohi,
                               __nv_bfloat16* __restrict__ olo)
{
    __shared__ float sh[8];
    long row = blockIdx.x;
    const float* p = att + row * C_DIM;
    int tid = threadIdx.x;
    float v[4];
    float m = -INFINITY;
#pragma unroll
    for (int i = 0; i < 4; i++) {
        v[i] = p[tid + i * 256];
        m = fmaxf(m, v[i]);
    }
#pragma unroll
    for (int o = 16; o > 0; o >>= 1)
        m = fmaxf(m, __shfl_down_sync(0xffffffffu, m, o));
    int lane = tid & 31, w = tid >> 5;
    if (lane == 0) sh[w] = m;
    __syncthreads();
    if (tid < 32) {
        m = (tid < 8) ? sh[tid] : -INFINITY;
#pragma unroll
        for (int o = 4; o > 0; o >>= 1)
            m = fmaxf(m, __shfl_down_sync(0xffffffffu, m, o));
        if (tid == 0) sh[0] = m;
    }
    __syncthreads();
    m = sh[0];
    __syncthreads();
    float e[4];
    float s = 0.f;
#pragma unroll
    for (int i = 0; i < 4; i++) {
        e[i] = expf(v[i] - m);
        s += e[i];
    }
#pragma unroll
    for (int o = 16; o > 0; o >>= 1)
        s += __shfl_down_sync(0xffffffffu, s, o);
    if (lane == 0) sh[w] = s;
    __syncthreads();
    if (tid < 32) {
        s = (tid < 8) ? sh[tid] : 0.f;
#pragma unroll
        for (int o = 4; o > 0; o >>= 1)
            s += __shfl_down_sync(0xffffffffu, s, o);
        if (tid == 0) sh[0] = s;
    }
    __syncthreads();
    float inv = 1.0f / sh[0];
#pragma unroll
    for (int i = 0; i < 4; i++) {
        int c = tid + i * 256;
        float y = e[i] * inv;
        __nv_bfloat16 hb = __float2bfloat16_rn(y);
        ohi[row * C_DIM + c] = hb;
        olo[row * C_DIM + c] = __float2bfloat16_rn(y - __bfloat162float(hb));
    }
}

static void launch_gemm(const __nv_bfloat16* Ahi, const __nv_bfloat16* Alo,
                        const __nv_bfloat16* Bhi, const __nv_bfloat16* Blo,
                        float* C, __nv_bfloat16* Ohi, __nv_bfloat16* Olo,
                        int M, int N, int K, int lda, int ldb, int ldc,
                        long sA, long sB, long sC, int batches,
                        const float* bias, const float* residual,
                        float scale, int act, int pe)
{
    dim3 grid(N / 256, M / 128, batches);
    gemm_sp<<<grid, 512, SM_TOT>>>(Ahi, Alo, Bhi, Blo, C, Ohi, Olo, K, lda, ldb, ldc,
                                   sA, sB, sC, bias, residual, scale, act, pe);
}

extern "C" void kernel_launch(void* const* d_in, const int* in_sizes, int n_in,
                              void* d_out, int out_size)
{
    const float* x        = (const float*)d_in[0];
    const float* fc_in_w  = (const float*)d_in[1];
    const float* fc_in_b  = (const float*)d_in[2];
    const float* ln_g     = (const float*)d_in[3];
    const float* ln_b     = (const float*)d_in[4];
    const float* qkv_w    = (const float*)d_in[5];
    const float* qkv_b    = (const float*)d_in[6];
    const float* proj_w   = (const float*)d_in[7];
    const float* proj_b   = (const float*)d_in[8];
    const float* fc_out_w = (const float*)d_in[9];
    const float* fc_out_b = (const float*)d_in[10];
    float* out = (float*)d_out;

    cudaFuncSetAttribute(gemm_sp, cudaFuncAttributeMaxDynamicSharedMemorySize, SM_TOT);

    __nv_bfloat16 *whi, *wlo, *xhi, *xlo, *ahi, *alo, *qhi, *qlo, *vhi, *vlo, *schi, *sclo, *smhi, *smlo;
    float *h0, *att, *pred;
    cudaGetSymbolAddress((void**)&whi, g_w_hi);
    cudaGetSymbolAddress((void**)&wlo, g_w_lo);
    cudaGetSymbolAddress((void**)&xhi, g_x_hi);
    cudaGetSymbolAddress((void**)&xlo, g_x_lo);
    cudaGetSymbolAddress((void**)&ahi, g_a_hi);
    cudaGetSymbolAddress((void**)&alo, g_a_lo);
    cudaGetSymbolAddress((void**)&qhi, g_qkv_hi);
    cudaGetSymbolAddress((void**)&qlo, g_qkv_lo);
    cudaGetSymbolAddress((void**)&vhi, g_vt_hi);
    cudaGetSymbolAddress((void**)&vlo, g_vt_lo);
    cudaGetSymbolAddress((void**)&schi, g_sc_hi);
    cudaGetSymbolAddress((void**)&sclo, g_sc_lo);
    cudaGetSymbolAddress((void**)&smhi, g_sm_hi);
    cudaGetSymbolAddress((void**)&smlo, g_sm_lo);
    cudaGetSymbolAddress((void**)&h0, g_h0);
    cudaGetSymbolAddress((void**)&att, g_att);
    cudaGetSymbolAddress((void**)&pred, g_pred);

    // split inputs/weights
    split_kernel<<<512, 256>>>(x, xhi, xlo, (long)M_TOT * C_DIM / 4);
    split_kernel<<<256, 256>>>(fc_in_w, whi + W_FCIN, wlo + W_FCIN, (long)C_DIM * C_DIM / 4);
    split_kernel<<<1024, 256>>>(qkv_w, whi + W_QKV, wlo + W_QKV, (long)4 * 3 * C_DIM * C_DIM / 4);
    split_kernel<<<512, 256>>>(proj_w, whi + W_PROJ, wlo + W_PROJ, (long)4 * C_DIM * C_DIM / 4);
    split_kernel<<<256, 256>>>(fc_out_w, whi + W_FCOUT, wlo + W_FCOUT, (long)C_DIM * C_DIM / 4);

    // h0 = x @ fc_in_w^T + fc_in_b    (fp32 out only)
    launch_gemm(xhi, xlo, whi + W_FCIN, wlo + W_FCIN, h0, nullptr, nullptr,
                M_TOT, C_DIM, C_DIM, C_DIM, C_DIM, C_DIM, 0, 0, 0, 1,
                fc_in_b, nullptr, 1.0f, 0, 0);

    // a = split(layernorm(h0))
    layernorm_kernel<<<M_TOT, 256>>>(h0, ln_g, ln_b, ahi, alo);

    for (int i = 0; i < 4; i++) {
        long wq = W_QKV + (long)i * 3 * C_DIM * C_DIM;
        long wp = W_PROJ + (long)i * C_DIM * C_DIM;

        // qkv = split(gelu(a @ qkv_w[i]^T + qkv_b[i]))   (split out only)
        launch_gemm(ahi, alo, whi + wq, wlo + wq, nullptr, qhi, qlo,
                    M_TOT, 3 * C_DIM, C_DIM, C_DIM, C_DIM, 3 * C_DIM, 0, 0, 0, 1,
                    qkv_b + (long)i * 3 * C_DIM, nullptr, 1.0f, 1, 0);

        // vt = split transpose of v
        transpose_v_bf<<<dim3(S_LEN / 32, C_DIM / 32, NB), dim3(32, 8)>>>(qhi, qlo, vhi, vlo);

        // scores = split(q @ k^T / C)   (split out only, batched)
        launch_gemm(qhi, qlo, qhi + C_DIM, qlo + C_DIM, nullptr, schi, sclo,
                    S_LEN, S_LEN, C_DIM, 3 * C_DIM, 3 * C_DIM, S_LEN,
                    (long)S_LEN * 3 * C_DIM, (long)S_LEN * 3 * C_DIM, (long)S_LEN * S_LEN,
                    NB, nullptr, nullptr, 1.0f / 1024.0f, 0, 0);

        // att = scores @ vt^T   (fp32 out, batched)
        launch_gemm(schi, sclo, vhi, vlo, att, nullptr, nullptr,
                    S_LEN, C_DIM, S_LEN, S_LEN, S_LEN, C_DIM,
                    (long)S_LEN * S_LEN, (long)C_DIM * S_LEN, (long)S_LEN * C_DIM,
                    NB, nullptr, nullptr, 1.0f, 0, 0);

        // sm = split(softmax(att))
        softmax_kernel<<<M_TOT, 256>>>(att, smhi, smlo);

        // a = split(gelu(sm @ proj_w[i]^T + proj_b[i]) [+ pred]); fp32 pred copy on i==0
        launch_gemm(smhi, smlo, whi + wp, wlo + wp,
                    (i == 0) ? pred : nullptr, ahi, alo,
                    M_TOT, C_DIM, C_DIM, C_DIM, C_DIM, C_DIM, 0, 0, 0, 1,
                    proj_b + (long)i * C_DIM, (i == 0) ? nullptr : pred, 1.0f, 1, 0);
    }

    // out = a @ fc_out_w^T + fc_out_b + pose_enc
    launch_gemm(ahi, alo, whi + W_FCOUT, wlo + W_FCOUT, out, nullptr, nullptr,
                M_TOT, C_DIM, C_DIM, C_DIM, C_DIM, C_DIM, 0, 0, 0, 1,
                fc_out_b, nullptr, 1.0f, 0, 1);
}

// round 9
// speedup vs baseline: 2.8801x; 2.0514x over previous
#include <cuda_runtime.h>
#include <cuda_fp16.h>
#include <math.h>
#include <stdint.h>

#define M_TOT 8192
#define C_DIM 1024
#define S_LEN 2048
#define NB 4

// ---------------- static scratch (no allocations allowed) ----------------
// fp32
__device__ float g_h0[M_TOT * C_DIM];
__device__ float g_att[M_TOT * C_DIM];
__device__ float g_pred[M_TOT * C_DIM];
// fp16 buffers
#define W_FCIN 0
#define W_QKV  1048576
#define W_PROJ 13631488
#define W_FCOUT 17825792
#define W_TOTAL 18874368
__device__ __half g_w_h[W_TOTAL];
__device__ __half g_x_h[M_TOT * C_DIM];
__device__ __half g_a_h[M_TOT * C_DIM];
__device__ __half g_qkv_h[(long)M_TOT * 3 * C_DIM];
__device__ __half g_vt_h[(long)NB * C_DIM * S_LEN];
__device__ __half g_sc_h[(long)NB * S_LEN * S_LEN];
__device__ __half g_sm_h[M_TOT * C_DIM];

// ---------------- helpers ----------------
__device__ __forceinline__ uint32_t smem_u32(const void* p) {
    uint32_t a;
    asm("{ .reg .u64 t; cvta.to.shared.u64 t, %1; cvt.u32.u64 %0, t; }" : "=r"(a) : "l"(p));
    return a;
}
__device__ __forceinline__ float gelu_f(float x) {
    return 0.5f * x * (1.0f + erff(x * 0.70710678118654752f));
}
__device__ __forceinline__ uint32_t h2_bits(__half2 v) {
    return *reinterpret_cast<uint32_t*>(&v);
}
__device__ __forceinline__ void ldsm4(uint32_t* r, uint32_t addr) {
    asm volatile("ldmatrix.sync.aligned.m8n8.x4.shared.b16 {%0,%1,%2,%3}, [%4];"
        : "=r"(r[0]), "=r"(r[1]), "=r"(r[2]), "=r"(r[3]) : "r"(addr));
}
__device__ __forceinline__ void ldsm2(uint32_t* r, uint32_t addr) {
    asm volatile("ldmatrix.sync.aligned.m8n8.x2.shared.b16 {%0,%1}, [%2];"
        : "=r"(r[0]), "=r"(r[1]) : "r"(addr));
}
__device__ __forceinline__ void mma16816(float* d, const uint32_t* a, const uint32_t* b) {
    asm volatile("mma.sync.aligned.m16n8k16.row.col.f32.f16.f16.f32 "
        "{%0,%1,%2,%3}, {%4,%5,%6,%7}, {%8,%9}, {%0,%1,%2,%3};"
        : "+f"(d[0]), "+f"(d[1]), "+f"(d[2]), "+f"(d[3])
        : "r"(a[0]), "r"(a[1]), "r"(a[2]), "r"(a[3]), "r"(b[0]), "r"(b[1]));
}
#define CP16(dst, src) \
    asm volatile("cp.async.ca.shared.global [%0], [%1], 16;" :: "r"(dst), "l"(src) : "memory")
#define CP_COMMIT() asm volatile("cp.async.commit_group;" ::: "memory")
#define CP_WAIT1() asm volatile("cp.async.wait_group 1;" ::: "memory")

// SMEM stage: A tile + B tile, each 128 rows x 32 fp16, row stride 80B.
#define ROW_B 80
#define OFF_A 0
#define OFF_B 10240
#define STAGE_B 20480
#define SM_TOT (2 * STAGE_B)

// D[M,N] = epi(scale * A[M,K] @ B[N,K]^T), fp16 inputs, single-pass HMMA,
// 2-stage cp.async. CTA 128x128, BK=32, 256 thr = 8 warps (2M x 4N), warp 64x32.
__global__ void __launch_bounds__(256, 2) gemm_fp16(
    const __half* __restrict__ A, const __half* __restrict__ B,
    float* __restrict__ C, __half* __restrict__ O,
    int K, int lda, int ldb, int ldc,
    long sA, long sB, long sC,
    const float* __restrict__ bias, const float* __restrict__ residual,
    float scale, int act, int pe)
{
    extern __shared__ char sm[];
    uint32_t sb = smem_u32(sm);

    int tid = threadIdx.x, wid = tid >> 5, lane = tid & 31;
    long bz = blockIdx.z;
    A += bz * sA; B += bz * sB;
    if (C) C += bz * sC;
    if (O) O += bz * sC;
    const float* res = residual ? residual + bz * sC : nullptr;
    long row0 = (long)blockIdx.y * 128, col0 = (long)blockIdx.x * 128;

    int wm = wid >> 2, wn = wid & 3;     // 2 x 4 warp grid
    int m0w = wm * 64, n0w = wn * 32;

    float acc[4][4][4];
#pragma unroll
    for (int i = 0; i < 4; i++)
#pragma unroll
        for (int j = 0; j < 4; j++)
#pragma unroll
            for (int e = 0; e < 4; e++) acc[i][j][e] = 0.f;

    // loader: row = tid>>1 (0..127), 16B groups sg, sg+1 of 4 per row-chunk
    const int r_ld = tid >> 1;
    const int sg = (tid & 1) * 2;
    const int NC = K >> 5;

    const __half* a_src = A + (row0 + r_ld) * lda + sg * 8;
    const __half* b_src = B + (col0 + r_ld) * ldb + sg * 8;
    const uint32_t stA = sb + OFF_A + r_ld * ROW_B + sg * 16;
    const uint32_t stB = sb + OFF_B + r_ld * ROW_B + sg * 16;

    auto issue = [&](int c, uint32_t bofs) {
        long ko = (long)c * 32;
        CP16(stA + bofs,      a_src + ko);
        CP16(stA + bofs + 16, a_src + ko + 8);
        CP16(stB + bofs,      b_src + ko);
        CP16(stB + bofs + 16, b_src + ko + 8);
    };

    // ldmatrix addresses (stage 0 base; add bofs, + ks*32 per k16 step)
    uint32_t a_addr[4], b_addr[4];
#pragma unroll
    for (int i = 0; i < 4; i++) {
        uint32_t r = m0w + i * 16 + (lane & 15);
        a_addr[i] = sb + OFF_A + r * ROW_B + (lane >> 4) * 16;
    }
#pragma unroll
    for (int j = 0; j < 4; j++) {
        uint32_t r = n0w + j * 8 + (lane & 7);
        b_addr[j] = sb + OFF_B + r * ROW_B + ((lane >> 3) & 1) * 16;
    }

    issue(0, 0); CP_COMMIT();
    if (NC > 1) issue(1, STAGE_B);
    CP_COMMIT();

    for (int c = 0; c < NC; c++) {
        CP_WAIT1();
        __syncthreads();
        uint32_t bofs = (c & 1) * STAGE_B;
#pragma unroll
        for (int ks = 0; ks < 2; ks++) {
            uint32_t ah[4][4], bh[4][2];
#pragma unroll
            for (int i = 0; i < 4; i++)
                ldsm4(ah[i], a_addr[i] + bofs + ks * 32);
#pragma unroll
            for (int j = 0; j < 4; j++)
                ldsm2(bh[j], b_addr[j] + bofs + ks * 32);
#pragma unroll
            for (int i = 0; i < 4; i++)
#pragma unroll
                for (int j = 0; j < 4; j++) mma16816(acc[i][j], ah[i], bh[j]);
        }
        __syncthreads();
        if (c + 2 < NC) issue(c + 2, (c & 1) * STAGE_B);
        CP_COMMIT();
    }

    // epilogue: thread holds C[r1][cc..cc+1], C[r1+8][cc..cc+1] per (i,j)
#pragma unroll
    for (int i = 0; i < 4; i++) {
        long r1 = row0 + m0w + i * 16 + (lane >> 2);
        long r2 = r1 + 8;
#pragma unroll
        for (int j = 0; j < 4; j++) {
            long cc = col0 + n0w + j * 8 + 2 * (lane & 3);
            float2 bi = bias ? *(const float2*)(bias + cc) : make_float2(0.f, 0.f);
            float v0 = acc[i][j][0] * scale + bi.x;
            float v1 = acc[i][j][1] * scale + bi.y;
            float v2 = acc[i][j][2] * scale + bi.x;
            float v3 = acc[i][j][3] * scale + bi.y;
            if (act) { v0 = gelu_f(v0); v1 = gelu_f(v1); v2 = gelu_f(v2); v3 = gelu_f(v3); }
            if (res) {
                float2 q1 = *(const float2*)(res + r1 * ldc + cc);
                float2 q2 = *(const float2*)(res + r2 * ldc + cc);
                v0 += q1.x; v1 += q1.y; v2 += q2.x; v3 += q2.y;
            }
            if (pe) {
                float d0 = expf((float)cc * (-2.0f / 1024.0f) * 6.9077552789821370521f);
                float d1 = expf((float)(cc + 1) * (-2.0f / 1024.0f) * 6.9077552789821370521f);
                int s1 = (int)(r1 & (S_LEN - 1)), s2 = (int)(r2 & (S_LEN - 1));
                float a10 = s1 * d0, a11 = s1 * d1, a20 = s2 * d0, a21 = s2 * d1;
                v0 += (s1 & 1) ? cosf(a10) : sinf(a10);
                v1 += (s1 & 1) ? cosf(a11) : sinf(a11);
                v2 += (s2 & 1) ? cosf(a20) : sinf(a20);
                v3 += (s2 & 1) ? cosf(a21) : sinf(a21);
            }
            if (C) {
                *(float2*)(C + r1 * ldc + cc) = make_float2(v0, v1);
                *(float2*)(C + r2 * ldc + cc) = make_float2(v2, v3);
            }
            if (O) {
                *(uint32_t*)(O + r1 * ldc + cc) = h2_bits(__floats2half2_rn(v0, v1));
                *(uint32_t*)(O + r2 * ldc + cc) = h2_bits(__floats2half2_rn(v2, v3));
            }
        }
    }
}

// fp32 -> fp16 convert, grid-stride over float4s
__global__ void cvt_kernel(const float* __restrict__ src,
                           __half* __restrict__ dst, long n4)
{
    long i = (long)blockIdx.x * blockDim.x + threadIdx.x;
    long stride = (long)gridDim.x * blockDim.x;
    for (; i < n4; i += stride) {
        float4 f = ((const float4*)src)[i];
        uint2 h;
        h.x = h2_bits(__floats2half2_rn(f.x, f.y));
        h.y = h2_bits(__floats2half2_rn(f.z, f.w));
        ((uint2*)dst)[i] = h;
    }
}

// vt[b][c][s] = qkv[b,s,2C+c]
__global__ void transpose_v_h(const __half* __restrict__ q,
                              __half* __restrict__ v)
{
    __shared__ __half t[32][34];
    int b = blockIdx.z;
    int s0 = blockIdx.x * 32, c0 = blockIdx.y * 32;
    int tx = threadIdx.x, ty = threadIdx.y;
    const __half* src = q + (long)b * S_LEN * 3 * C_DIM + 2 * C_DIM;
#pragma unroll
    for (int i = 0; i < 32; i += 8)
        t[ty + i][tx] = src[(long)(s0 + ty + i) * (3 * C_DIM) + c0 + tx];
    __syncthreads();
    __half* dst = v + (long)b * C_DIM * S_LEN;
#pragma unroll
    for (int i = 0; i < 32; i += 8)
        dst[(long)(c0 + ty + i) * S_LEN + s0 + tx] = t[tx][ty + i];
}

// layernorm over last dim (1024), fp32 in -> fp16 out
__global__ void layernorm_kernel(const float* __restrict__ h,
                                 const float* __restrict__ g,
                                 const float* __restrict__ b,
                                 __half* __restrict__ oh)
{
    __shared__ float sa[8], sb2[8];
    long row = blockIdx.x;
    const float* p = h + row * C_DIM;
    int tid = threadIdx.x;
    float v[4];
    float s1 = 0.f, s2 = 0.f;
#pragma unroll
    for (int i = 0; i < 4; i++) {
        v[i] = p[tid + i * 256];
        s1 += v[i];
        s2 += v[i] * v[i];
    }
#pragma unroll
    for (int o = 16; o > 0; o >>= 1) {
        s1 += __shfl_down_sync(0xffffffffu, s1, o);
        s2 += __shfl_down_sync(0xffffffffu, s2, o);
    }
    int lane = tid & 31, w = tid >> 5;
    if (lane == 0) { sa[w] = s1; sb2[w] = s2; }
    __syncthreads();
    if (tid < 32) {
        s1 = (tid < 8) ? sa[tid] : 0.f;
        s2 = (tid < 8) ? sb2[tid] : 0.f;
#pragma unroll
        for (int o = 4; o > 0; o >>= 1) {
            s1 += __shfl_down_sync(0xffffffffu, s1, o);
            s2 += __shfl_down_sync(0xffffffffu, s2, o);
        }
        if (tid == 0) { sa[0] = s1; sb2[0] = s2; }
    }
    __syncthreads();
    float mu = sa[0] * (1.0f / 1024.0f);
    float var = sb2[0] * (1.0f / 1024.0f) - mu * mu;
    float inv = rsqrtf(var + 1e-5f);
#pragma unroll
    for (int i = 0; i < 4; i++) {
        int c = tid + i * 256;
        float y = (v[i] - mu) * inv * g[c] + b[c];
        oh[row * C_DIM + c] = __float2half_rn(y);
    }
}

// softmax over last dim (1024), fp32 in -> fp16 out
__global__ void softmax_kernel(const float* __restrict__ att,
                               __half* __restrict__ oh)
{
    __shared__ float sh[8];
    long row = blockIdx.x;
    const float* p = att + row * C_DIM;
    int tid = threadIdx.x;
    float v[4];
    float m = -INFINITY;
#pragma unroll
    for (int i = 0; i < 4; i++) {
        v[i] = p[tid + i * 256];
        m = fmaxf(m, v[i]);
    }
#pragma unroll
    for (int o = 16; o > 0; o >>= 1)
        m = fmaxf(m, __shfl_down_sync(0xffffffffu, m, o));
    int lane = tid & 31, w = tid >> 5;
    if (lane == 0) sh[w] = m;
    __syncthreads();
    if (tid < 32) {
        m = (tid < 8) ? sh[tid] : -INFINITY;
#pragma unroll
        for (int o = 4; o > 0; o >>= 1)
            m = fmaxf(m, __shfl_down_sync(0xffffffffu, m, o));
        if (tid == 0) sh[0] = m;
    }
    __syncthreads();
    m = sh[0];
    __syncthreads();
    float e[4];
    float s = 0.f;
#pragma unroll
    for (int i = 0; i < 4; i++) {
        e[i] = expf(v[i] - m);
        s += e[i];
    }
#pragma unroll
    for (int o = 16; o > 0; o >>= 1)
        s += __shfl_down_sync(0xffffffffu, s, o);
    if (lane == 0) sh[w] = s;
    __syncthreads();
    if (tid < 32) {
        s = (tid < 8) ? sh[tid] : 0.f;
#pragma unroll
        for (int o = 4; o > 0; o >>= 1)
            s += __shfl_down_sync(0xffffffffu, s, o);
        if (tid == 0) sh[0] = s;
    }
    __syncthreads();
    float inv = 1.0f / sh[0];
#pragma unroll
    for (int i = 0; i < 4; i++) {
        int c = tid + i * 256;
        oh[row * C_DIM + c] = __float2half_rn(e[i] * inv);
    }
}

static void launch_gemm(const __half* A, const __half* B,
                        float* C, __half* O,
                        int M, int N, int K, int lda, int ldb, int ldc,
                        long sA, long sB, long sC, int batches,
                        const float* bias, const float* residual,
                        float scale, int act, int pe)
{
    dim3 grid(N / 128, M / 128, batches);
    gemm_fp16<<<grid, 256, SM_TOT>>>(A, B, C, O, K, lda, ldb, ldc,
                                     sA, sB, sC, bias, residual, scale, act, pe);
}

extern "C" void kernel_launch(void* const* d_in, const int* in_sizes, int n_in,
                              void* d_out, int out_size)
{
    const float* x        = (const float*)d_in[0];
    const float* fc_in_w  = (const float*)d_in[1];
    const float* fc_in_b  = (const float*)d_in[2];
    const float* ln_g     = (const float*)d_in[3];
    const float* ln_b     = (const float*)d_in[4];
    const float* qkv_w    = (const float*)d_in[5];
    const float* qkv_b    = (const float*)d_in[6];
    const float* proj_w   = (const float*)d_in[7];
    const float* proj_b   = (const float*)d_in[8];
    const float* fc_out_w = (const float*)d_in[9];
    const float* fc_out_b = (const float*)d_in[10];
    float* out = (float*)d_out;

    cudaFuncSetAttribute(gemm_fp16, cudaFuncAttributeMaxDynamicSharedMemorySize, SM_TOT);

    __half *wh, *xh, *ah, *qh, *vh, *sch, *smh;
    float *h0, *att, *pred;
    cudaGetSymbolAddress((void**)&wh, g_w_h);
    cudaGetSymbolAddress((void**)&xh, g_x_h);
    cudaGetSymbolAddress((void**)&ah, g_a_h);
    cudaGetSymbolAddress((void**)&qh, g_qkv_h);
    cudaGetSymbolAddress((void**)&vh, g_vt_h);
    cudaGetSymbolAddress((void**)&sch, g_sc_h);
    cudaGetSymbolAddress((void**)&smh, g_sm_h);
    cudaGetSymbolAddress((void**)&h0, g_h0);
    cudaGetSymbolAddress((void**)&att, g_att);
    cudaGetSymbolAddress((void**)&pred, g_pred);

    // convert inputs/weights to fp16
    cvt_kernel<<<512, 256>>>(x, xh, (long)M_TOT * C_DIM / 4);
    cvt_kernel<<<256, 256>>>(fc_in_w, wh + W_FCIN, (long)C_DIM * C_DIM / 4);
    cvt_kernel<<<1024, 256>>>(qkv_w, wh + W_QKV, (long)4 * 3 * C_DIM * C_DIM / 4);
    cvt_kernel<<<512, 256>>>(proj_w, wh + W_PROJ, (long)4 * C_DIM * C_DIM / 4);
    cvt_kernel<<<256, 256>>>(fc_out_w, wh + W_FCOUT, (long)C_DIM * C_DIM / 4);

    // h0 = x @ fc_in_w^T + fc_in_b    (fp32 out only)
    launch_gemm(xh, wh + W_FCIN, h0, nullptr,
                M_TOT, C_DIM, C_DIM, C_DIM, C_DIM, C_DIM, 0, 0, 0, 1,
                fc_in_b, nullptr, 1.0f, 0, 0);

    // a = fp16(layernorm(h0))
    layernorm_kernel<<<M_TOT, 256>>>(h0, ln_g, ln_b, ah);

    for (int i = 0; i < 4; i++) {
        long wq = W_QKV + (long)i * 3 * C_DIM * C_DIM;
        long wp = W_PROJ + (long)i * C_DIM * C_DIM;

        // qkv = fp16(gelu(a @ qkv_w[i]^T + qkv_b[i]))   (fp16 out only)
        launch_gemm(ah, wh + wq, nullptr, qh,
                    M_TOT, 3 * C_DIM, C_DIM, C_DIM, C_DIM, 3 * C_DIM, 0, 0, 0, 1,
                    qkv_b + (long)i * 3 * C_DIM, nullptr, 1.0f, 1, 0);

        // vt = transpose of v
        transpose_v_h<<<dim3(S_LEN / 32, C_DIM / 32, NB), dim3(32, 8)>>>(qh, vh);

        // scores = fp16(q @ k^T / C)   (fp16 out only, batched)
        launch_gemm(qh, qh + C_DIM, nullptr, sch,
                    S_LEN, S_LEN, C_DIM, 3 * C_DIM, 3 * C_DIM, S_LEN,
                    (long)S_LEN * 3 * C_DIM, (long)S_LEN * 3 * C_DIM, (long)S_LEN * S_LEN,
                    NB, nullptr, nullptr, 1.0f / 1024.0f, 0, 0);

        // att = scores @ vt^T   (fp32 out, batched)
        launch_gemm(sch, vh, att, nullptr,
                    S_LEN, C_DIM, S_LEN, S_LEN, S_LEN, C_DIM,
                    (long)S_LEN * S_LEN, (long)C_DIM * S_LEN, (long)S_LEN * C_DIM,
                    NB, nullptr, nullptr, 1.0f, 0, 0);

        // sm = fp16(softmax(att))
        softmax_kernel<<<M_TOT, 256>>>(att, smh);

        // a = fp16(gelu(sm @ proj_w[i]^T + proj_b[i]) [+ pred]); fp32 pred copy on i==0
        launch_gemm(smh, wh + wp, (i == 0) ? pred : nullptr, ah,
                    M_TOT, C_DIM, C_DIM, C_DIM, C_DIM, C_DIM, 0, 0, 0, 1,
                    proj_b + (long)i * C_DIM, (i == 0) ? nullptr : pred, 1.0f, 1, 0);
    }

    // out = a @ fc_out_w^T + fc_out_b + pose_enc
    launch_gemm(ah, wh + W_FCOUT, out, nullptr,
                M_TOT, C_DIM, C_DIM, C_DIM, C_DIM, C_DIM, 0, 0, 0, 1,
                fc_out_b, nullptr, 1.0f, 0, 1);
}

// round 10
// speedup vs baseline: 3.4858x; 1.2103x over previous
#include <cuda_runtime.h>
#include <cuda_fp16.h>
#include <math.h>
#include <stdint.h>

#define M_TOT 8192
#define C_DIM 1024
#define S_LEN 2048
#define NB 4

// ---------------- static scratch (no allocations allowed) ----------------
// fp32
__device__ float g_h0[M_TOT * C_DIM];
__device__ float g_att[M_TOT * C_DIM];
__device__ float g_pred[M_TOT * C_DIM];
// fp16 buffers
#define W_FCIN 0
#define W_QKV  1048576
#define W_PROJ 13631488
#define W_FCOUT 17825792
#define W_TOTAL 18874368
__device__ __half g_w_h[W_TOTAL];
__device__ __half g_x_h[M_TOT * C_DIM];
__device__ __half g_a_h[M_TOT * C_DIM];
__device__ __half g_qkv_h[(long)M_TOT * 3 * C_DIM];
__device__ __half g_kt_h[(long)NB * C_DIM * S_LEN];
__device__ __half g_vt_h[(long)NB * C_DIM * S_LEN];
__device__ __half g_m1_h[(long)NB * C_DIM * C_DIM];
__device__ __half g_sm_h[M_TOT * C_DIM];

// ---------------- helpers ----------------
__device__ __forceinline__ uint32_t smem_u32(const void* p) {
    uint32_t a;
    asm("{ .reg .u64 t; cvta.to.shared.u64 t, %1; cvt.u32.u64 %0, t; }" : "=r"(a) : "l"(p));
    return a;
}
__device__ __forceinline__ float gelu_f(float x) {
    return 0.5f * x * (1.0f + erff(x * 0.70710678118654752f));
}
__device__ __forceinline__ uint32_t h2_bits(__half2 v) {
    return *reinterpret_cast<uint32_t*>(&v);
}
__device__ __forceinline__ void ldsm4(uint32_t* r, uint32_t addr) {
    asm volatile("ldmatrix.sync.aligned.m8n8.x4.shared.b16 {%0,%1,%2,%3}, [%4];"
        : "=r"(r[0]), "=r"(r[1]), "=r"(r[2]), "=r"(r[3]) : "r"(addr));
}
__device__ __forceinline__ void ldsm2(uint32_t* r, uint32_t addr) {
    asm volatile("ldmatrix.sync.aligned.m8n8.x2.shared.b16 {%0,%1}, [%2];"
        : "=r"(r[0]), "=r"(r[1]) : "r"(addr));
}
__device__ __forceinline__ void mma16816(float* d, const uint32_t* a, const uint32_t* b) {
    asm volatile("mma.sync.aligned.m16n8k16.row.col.f32.f16.f16.f32 "
        "{%0,%1,%2,%3}, {%4,%5,%6,%7}, {%8,%9}, {%0,%1,%2,%3};"
        : "+f"(d[0]), "+f"(d[1]), "+f"(d[2]), "+f"(d[3])
        : "r"(a[0]), "r"(a[1]), "r"(a[2]), "r"(a[3]), "r"(b[0]), "r"(b[1]));
}
#define CP16(dst, src) \
    asm volatile("cp.async.ca.shared.global [%0], [%1], 16;" :: "r"(dst), "l"(src) : "memory")
#define CP_COMMIT() asm volatile("cp.async.commit_group;" ::: "memory")
#define CP_WAIT1() asm volatile("cp.async.wait_group 1;" ::: "memory")

// SMEM stage: A tile + B tile, each 128 rows x 32 fp16, row stride 80B.
#define ROW_B 80
#define OFF_A 0
#define OFF_B 10240
#define STAGE_B 20480
#define SM_TOT (2 * STAGE_B)

// D[M,N] = epi(scale * A[M,K] @ B[N,K]^T), fp16 inputs, single-pass HMMA,
// 2-stage cp.async. CTA 128x128, BK=32, 256 thr = 8 warps (2M x 4N), warp 64x32.
__global__ void __launch_bounds__(256, 2) gemm_fp16(
    const __half* __restrict__ A, const __half* __restrict__ B,
    float* __restrict__ C, __half* __restrict__ O,
    int K, int lda, int ldb, int ldc,
    long sA, long sB, long sC,
    const float* __restrict__ bias, const float* __restrict__ residual,
    float scale, int act, int pe)
{
    extern __shared__ char sm[];
    uint32_t sb = smem_u32(sm);

    int tid = threadIdx.x, wid = tid >> 5, lane = tid & 31;
    long bz = blockIdx.z;
    A += bz * sA; B += bz * sB;
    if (C) C += bz * sC;
    if (O) O += bz * sC;
    const float* res = residual ? residual + bz * sC : nullptr;
    long row0 = (long)blockIdx.y * 128, col0 = (long)blockIdx.x * 128;

    int wm = wid >> 2, wn = wid & 3;     // 2 x 4 warp grid
    int m0w = wm * 64, n0w = wn * 32;

    float acc[4][4][4];
#pragma unroll
    for (int i = 0; i < 4; i++)
#pragma unroll
        for (int j = 0; j < 4; j++)
#pragma unroll
            for (int e = 0; e < 4; e++) acc[i][j][e] = 0.f;

    // loader: row = tid>>1 (0..127), 16B groups sg, sg+1 of 4 per row-chunk
    const int r_ld = tid >> 1;
    const int sg = (tid & 1) * 2;
    const int NC = K >> 5;

    const __half* a_src = A + (row0 + r_ld) * lda + sg * 8;
    const __half* b_src = B + (col0 + r_ld) * ldb + sg * 8;
    const uint32_t stA = sb + OFF_A + r_ld * ROW_B + sg * 16;
    const uint32_t stB = sb + OFF_B + r_ld * ROW_B + sg * 16;

    auto issue = [&](int c, uint32_t bofs) {
        long ko = (long)c * 32;
        CP16(stA + bofs,      a_src + ko);
        CP16(stA + bofs + 16, a_src + ko + 8);
        CP16(stB + bofs,      b_src + ko);
        CP16(stB + bofs + 16, b_src + ko + 8);
    };

    // ldmatrix addresses (stage 0 base; add bofs, + ks*32 per k16 step)
    uint32_t a_addr[4], b_addr[4];
#pragma unroll
    for (int i = 0; i < 4; i++) {
        uint32_t r = m0w + i * 16 + (lane & 15);
        a_addr[i] = sb + OFF_A + r * ROW_B + (lane >> 4) * 16;
    }
#pragma unroll
    for (int j = 0; j < 4; j++) {
        uint32_t r = n0w + j * 8 + (lane & 7);
        b_addr[j] = sb + OFF_B + r * ROW_B + ((lane >> 3) & 1) * 16;
    }

    issue(0, 0); CP_COMMIT();
    if (NC > 1) issue(1, STAGE_B);
    CP_COMMIT();

    for (int c = 0; c < NC; c++) {
        CP_WAIT1();
        __syncthreads();
        uint32_t bofs = (c & 1) * STAGE_B;
#pragma unroll
        for (int ks = 0; ks < 2; ks++) {
            uint32_t ah[4][4], bh[4][2];
#pragma unroll
            for (int i = 0; i < 4; i++)
                ldsm4(ah[i], a_addr[i] + bofs + ks * 32);
#pragma unroll
            for (int j = 0; j < 4; j++)
                ldsm2(bh[j], b_addr[j] + bofs + ks * 32);
#pragma unroll
            for (int i = 0; i < 4; i++)
#pragma unroll
                for (int j = 0; j < 4; j++) mma16816(acc[i][j], ah[i], bh[j]);
        }
        __syncthreads();
        if (c + 2 < NC) issue(c + 2, (c & 1) * STAGE_B);
        CP_COMMIT();
    }

    // epilogue: thread holds C[r1][cc..cc+1], C[r1+8][cc..cc+1] per (i,j)
#pragma unroll
    for (int i = 0; i < 4; i++) {
        long r1 = row0 + m0w + i * 16 + (lane >> 2);
        long r2 = r1 + 8;
#pragma unroll
        for (int j = 0; j < 4; j++) {
            long cc = col0 + n0w + j * 8 + 2 * (lane & 3);
            float2 bi = bias ? *(const float2*)(bias + cc) : make_float2(0.f, 0.f);
            float v0 = acc[i][j][0] * scale + bi.x;
            float v1 = acc[i][j][1] * scale + bi.y;
            float v2 = acc[i][j][2] * scale + bi.x;
            float v3 = acc[i][j][3] * scale + bi.y;
            if (act) { v0 = gelu_f(v0); v1 = gelu_f(v1); v2 = gelu_f(v2); v3 = gelu_f(v3); }
            if (res) {
                float2 q1 = *(const float2*)(res + r1 * ldc + cc);
                float2 q2 = *(const float2*)(res + r2 * ldc + cc);
                v0 += q1.x; v1 += q1.y; v2 += q2.x; v3 += q2.y;
            }
            if (pe) {
                float d0 = expf((float)cc * (-2.0f / 1024.0f) * 6.9077552789821370521f);
                float d1 = expf((float)(cc + 1) * (-2.0f / 1024.0f) * 6.9077552789821370521f);
                int s1 = (int)(r1 & (S_LEN - 1)), s2 = (int)(r2 & (S_LEN - 1));
                float a10 = s1 * d0, a11 = s1 * d1, a20 = s2 * d0, a21 = s2 * d1;
                v0 += (s1 & 1) ? cosf(a10) : sinf(a10);
                v1 += (s1 & 1) ? cosf(a11) : sinf(a11);
                v2 += (s2 & 1) ? cosf(a20) : sinf(a20);
                v3 += (s2 & 1) ? cosf(a21) : sinf(a21);
            }
            if (C) {
                *(float2*)(C + r1 * ldc + cc) = make_float2(v0, v1);
                *(float2*)(C + r2 * ldc + cc) = make_float2(v2, v3);
            }
            if (O) {
                *(uint32_t*)(O + r1 * ldc + cc) = h2_bits(__floats2half2_rn(v0, v1));
                *(uint32_t*)(O + r2 * ldc + cc) = h2_bits(__floats2half2_rn(v2, v3));
            }
        }
    }
}

// fused fp32 -> fp16 convert of 5 tensors, grid-stride over float4s
__global__ void cvt5_kernel(const float* s0, __half* d0, long n0,
                            const float* s1, __half* d1, long n1,
                            const float* s2, __half* d2, long n2,
                            const float* s3, __half* d3, long n3,
                            const float* s4, __half* d4, long n4)
{
    long tot = n0 + n1 + n2 + n3 + n4;
    long i = (long)blockIdx.x * blockDim.x + threadIdx.x;
    long stride = (long)gridDim.x * blockDim.x;
    for (; i < tot; i += stride) {
        const float* s; __half* d; long k = i;
        if (k < n0) { s = s0; d = d0; }
        else if ((k -= n0) < n1) { s = s1; d = d1; }
        else if ((k -= n1) < n2) { s = s2; d = d2; }
        else if ((k -= n2) < n3) { s = s3; d = d3; }
        else { k -= n3; s = s4; d = d4; }
        float4 f = ((const float4*)s)[k];
        uint2 h;
        h.x = h2_bits(__floats2half2_rn(f.x, f.y));
        h.y = h2_bits(__floats2half2_rn(f.z, f.w));
        ((uint2*)d)[k] = h;
    }
}

// dst[b][c][s] = qkv[b, s, co + c]   (transpose one of q/k/v out of packed qkv)
__global__ void transpose_h(const __half* __restrict__ q,
                            __half* __restrict__ dst_, int co)
{
    __shared__ __half t[32][34];
    int b = blockIdx.z;
    int s0 = blockIdx.x * 32, c0 = blockIdx.y * 32;
    int tx = threadIdx.x, ty = threadIdx.y;
    const __half* src = q + (long)b * S_LEN * 3 * C_DIM + co;
#pragma unroll
    for (int i = 0; i < 32; i += 8)
        t[ty + i][tx] = src[(long)(s0 + ty + i) * (3 * C_DIM) + c0 + tx];
    __syncthreads();
    __half* dst = dst_ + (long)b * C_DIM * S_LEN;
#pragma unroll
    for (int i = 0; i < 32; i += 8)
        dst[(long)(c0 + ty + i) * S_LEN + s0 + tx] = t[tx][ty + i];
}

// layernorm over last dim (1024), fp32 in -> fp16 out
__global__ void layernorm_kernel(const float* __restrict__ h,
                                 const float* __restrict__ g,
                                 const float* __restrict__ b,
                                 __half* __restrict__ oh)
{
    __shared__ float sa[8], sb2[8];
    long row = blockIdx.x;
    const float* p = h + row * C_DIM;
    int tid = threadIdx.x;
    float v[4];
    float s1 = 0.f, s2 = 0.f;
#pragma unroll
    for (int i = 0; i < 4; i++) {
        v[i] = p[tid + i * 256];
        s1 += v[i];
        s2 += v[i] * v[i];
    }
#pragma unroll
    for (int o = 16; o > 0; o >>= 1) {
        s1 += __shfl_down_sync(0xffffffffu, s1, o);
        s2 += __shfl_down_sync(0xffffffffu, s2, o);
    }
    int lane = tid & 31, w = tid >> 5;
    if (lane == 0) { sa[w] = s1; sb2[w] = s2; }
    __syncthreads();
    if (tid < 32) {
        s1 = (tid < 8) ? sa[tid] : 0.f;
        s2 = (tid < 8) ? sb2[tid] : 0.f;
#pragma unroll
        for (int o = 4; o > 0; o >>= 1) {
            s1 += __shfl_down_sync(0xffffffffu, s1, o);
            s2 += __shfl_down_sync(0xffffffffu, s2, o);
        }
        if (tid == 0) { sa[0] = s1; sb2[0] = s2; }
    }
    __syncthreads();
    float mu = sa[0] * (1.0f / 1024.0f);
    float var = sb2[0] * (1.0f / 1024.0f) - mu * mu;
    float inv = rsqrtf(var + 1e-5f);
#pragma unroll
    for (int i = 0; i < 4; i++) {
        int c = tid + i * 256;
        float y = (v[i] - mu) * inv * g[c] + b[c];
        oh[row * C_DIM + c] = __float2half_rn(y);
    }
}

// softmax over last dim (1024), fp32 in -> fp16 out
__global__ void softmax_kernel(const float* __restrict__ att,
                               __half* __restrict__ oh)
{
    __shared__ float sh[8];
    long row = blockIdx.x;
    const float* p = att + row * C_DIM;
    int tid = threadIdx.x;
    float v[4];
    float m = -INFINITY;
#pragma unroll
    for (int i = 0; i < 4; i++) {
        v[i] = p[tid + i * 256];
        m = fmaxf(m, v[i]);
    }
#pragma unroll
    for (int o = 16; o > 0; o >>= 1)
        m = fmaxf(m, __shfl_down_sync(0xffffffffu, m, o));
    int lane = tid & 31, w = tid >> 5;
    if (lane == 0) sh[w] = m;
    __syncthreads();
    if (tid < 32) {
        m = (tid < 8) ? sh[tid] : -INFINITY;
#pragma unroll
        for (int o = 4; o > 0; o >>= 1)
            m = fmaxf(m, __shfl_down_sync(0xffffffffu, m, o));
        if (tid == 0) sh[0] = m;
    }
    __syncthreads();
    m = sh[0];
    __syncthreads();
    float e[4];
    float s = 0.f;
#pragma unroll
    for (int i = 0; i < 4; i++) {
        e[i] = expf(v[i] - m);
        s += e[i];
    }
#pragma unroll
    for (int o = 16; o > 0; o >>= 1)
        s += __shfl_down_sync(0xffffffffu, s, o);
    if (lane == 0) sh[w] = s;
    __syncthreads();
    if (tid < 32) {
        s = (tid < 8) ? sh[tid] : 0.f;
#pragma unroll
        for (int o = 4; o > 0; o >>= 1)
            s += __shfl_down_sync(0xffffffffu, s, o);
        if (tid == 0) sh[0] = s;
    }
    __syncthreads();
    float inv = 1.0f / sh[0];
#pragma unroll
    for (int i = 0; i < 4; i++) {
        int c = tid + i * 256;
        oh[row * C_DIM + c] = __float2half_rn(e[i] * inv);
    }
}

static void launch_gemm(const __half* A, const __half* B,
                        float* C, __half* O,
                        int M, int N, int K, int lda, int ldb, int ldc,
                        long sA, long sB, long sC, int batches,
                        const float* bias, const float* residual,
                        float scale, int act, int pe)
{
    dim3 grid(N / 128, M / 128, batches);
    gemm_fp16<<<grid, 256, SM_TOT>>>(A, B, C, O, K, lda, ldb, ldc,
                                     sA, sB, sC, bias, residual, scale, act, pe);
}

extern "C" void kernel_launch(void* const* d_in, const int* in_sizes, int n_in,
                              void* d_out, int out_size)
{
    const float* x        = (const float*)d_in[0];
    const float* fc_in_w  = (const float*)d_in[1];
    const float* fc_in_b  = (const float*)d_in[2];
    const float* ln_g     = (const float*)d_in[3];
    const float* ln_b     = (const float*)d_in[4];
    const float* qkv_w    = (const float*)d_in[5];
    const float* qkv_b    = (const float*)d_in[6];
    const float* proj_w   = (const float*)d_in[7];
    const float* proj_b   = (const float*)d_in[8];
    const float* fc_out_w = (const float*)d_in[9];
    const float* fc_out_b = (const float*)d_in[10];
    float* out = (float*)d_out;

    cudaFuncSetAttribute(gemm_fp16, cudaFuncAttributeMaxDynamicSharedMemorySize, SM_TOT);

    __half *wh, *xh, *ah, *qh, *kt, *vt, *m1, *smh;
    float *h0, *att, *pred;
    cudaGetSymbolAddress((void**)&wh, g_w_h);
    cudaGetSymbolAddress((void**)&xh, g_x_h);
    cudaGetSymbolAddress((void**)&ah, g_a_h);
    cudaGetSymbolAddress((void**)&qh, g_qkv_h);
    cudaGetSymbolAddress((void**)&kt, g_kt_h);
    cudaGetSymbolAddress((void**)&vt, g_vt_h);
    cudaGetSymbolAddress((void**)&m1, g_m1_h);
    cudaGetSymbolAddress((void**)&smh, g_sm_h);
    cudaGetSymbolAddress((void**)&h0, g_h0);
    cudaGetSymbolAddress((void**)&att, g_att);
    cudaGetSymbolAddress((void**)&pred, g_pred);

    // convert all inputs/weights to fp16 in ONE launch
    cvt5_kernel<<<1024, 256>>>(
        x, xh, (long)M_TOT * C_DIM / 4,
        fc_in_w, wh + W_FCIN, (long)C_DIM * C_DIM / 4,
        qkv_w, wh + W_QKV, (long)4 * 3 * C_DIM * C_DIM / 4,
        proj_w, wh + W_PROJ, (long)4 * C_DIM * C_DIM / 4,
        fc_out_w, wh + W_FCOUT, (long)C_DIM * C_DIM / 4);

    // h0 = x @ fc_in_w^T + fc_in_b    (fp32 out only)
    launch_gemm(xh, wh + W_FCIN, h0, nullptr,
                M_TOT, C_DIM, C_DIM, C_DIM, C_DIM, C_DIM, 0, 0, 0, 1,
                fc_in_b, nullptr, 1.0f, 0, 0);

    // a = fp16(layernorm(h0))
    layernorm_kernel<<<M_TOT, 256>>>(h0, ln_g, ln_b, ah);

    for (int i = 0; i < 4; i++) {
        long wq = W_QKV + (long)i * 3 * C_DIM * C_DIM;
        long wp = W_PROJ + (long)i * C_DIM * C_DIM;

        // qkv = fp16(gelu(a @ qkv_w[i]^T + qkv_b[i]))
        launch_gemm(ah, wh + wq, nullptr, qh,
                    M_TOT, 3 * C_DIM, C_DIM, C_DIM, C_DIM, 3 * C_DIM, 0, 0, 0, 1,
                    qkv_b + (long)i * 3 * C_DIM, nullptr, 1.0f, 1, 0);

        // kT, vT transposes
        transpose_h<<<dim3(S_LEN / 32, C_DIM / 32, NB), dim3(32, 8)>>>(qh, kt, C_DIM);
        transpose_h<<<dim3(S_LEN / 32, C_DIM / 32, NB), dim3(32, 8)>>>(qh, vt, 2 * C_DIM);

        // M1[c'][c] = sum_t v[t][c'] k[t][c]  = (k^T v)^T   (NT: A=vT, B=kT; batched)
        launch_gemm(vt, kt, nullptr, m1,
                    C_DIM, C_DIM, S_LEN, S_LEN, S_LEN, C_DIM,
                    (long)C_DIM * S_LEN, (long)C_DIM * S_LEN, (long)C_DIM * C_DIM,
                    NB, nullptr, nullptr, 1.0f, 0, 0);

        // att = q @ M1^T / 1024 = (q@k^T/C)@v   (fp32 out, batched; q strided in qkv)
        launch_gemm(qh, m1, att, nullptr,
                    S_LEN, C_DIM, C_DIM, 3 * C_DIM, C_DIM, C_DIM,
                    (long)S_LEN * 3 * C_DIM, (long)C_DIM * C_DIM, (long)S_LEN * C_DIM,
                    NB, nullptr, nullptr, 1.0f / 1024.0f, 0, 0);

        // sm = fp16(softmax(att))
        softmax_kernel<<<M_TOT, 256>>>(att, smh);

        // a = fp16(gelu(sm @ proj_w[i]^T + proj_b[i]) [+ pred]); fp32 pred copy on i==0
        launch_gemm(smh, wh + wp, (i == 0) ? pred : nullptr, ah,
                    M_TOT, C_DIM, C_DIM, C_DIM, C_DIM, C_DIM, 0, 0, 0, 1,
                    proj_b + (long)i * C_DIM, (i == 0) ? nullptr : pred, 1.0f, 1, 0);
    }

    // out = a @ fc_out_w^T + fc_out_b + pose_enc
    launch_gemm(ah, wh + W_FCOUT, out, nullptr,
                M_TOT, C_DIM, C_DIM, C_DIM, C_DIM, C_DIM, 0, 0, 0, 1,
                fc_out_b, nullptr, 1.0f, 0, 1);
}

// round 11
// speedup vs baseline: 3.8572x; 1.1066x over previous
#include <cuda_runtime.h>
#include <cuda_fp16.h>
#include <math.h>
#include <stdint.h>

#define M_TOT 8192
#define C_DIM 1024
#define S_LEN 2048
#define NB 4

// ---------------- static scratch (no allocations allowed) ----------------
// fp32
__device__ float g_h0[M_TOT * C_DIM];
__device__ float g_att[M_TOT * C_DIM];
__device__ float g_pred[M_TOT * C_DIM];
// fp16 buffers
#define W_FCIN 0
#define W_QKV  1048576
#define W_PROJ 13631488
#define W_FCOUT 17825792
#define W_TOTAL 18874368
__device__ __half g_w_h[W_TOTAL];
__device__ __half g_x_h[M_TOT * C_DIM];
__device__ __half g_a_h[M_TOT * C_DIM];
__device__ __half g_qkv_h[(long)M_TOT * 3 * C_DIM];
__device__ __half g_kt_h[(long)NB * C_DIM * S_LEN];
__device__ __half g_vt_h[(long)NB * C_DIM * S_LEN];
__device__ __half g_m1_h[(long)NB * C_DIM * C_DIM];
__device__ __half g_sm_h[M_TOT * C_DIM];

// ---------------- helpers ----------------
__device__ __forceinline__ uint32_t smem_u32(const void* p) {
    uint32_t a;
    asm("{ .reg .u64 t; cvta.to.shared.u64 t, %1; cvt.u32.u64 %0, t; }" : "=r"(a) : "l"(p));
    return a;
}
__device__ __forceinline__ float gelu_f(float x) {
    return 0.5f * x * (1.0f + erff(x * 0.70710678118654752f));
}
__device__ __forceinline__ uint32_t h2_bits(__half2 v) {
    return *reinterpret_cast<uint32_t*>(&v);
}
__device__ __forceinline__ void ldsm4(uint32_t* r, uint32_t addr) {
    asm volatile("ldmatrix.sync.aligned.m8n8.x4.shared.b16 {%0,%1,%2,%3}, [%4];"
        : "=r"(r[0]), "=r"(r[1]), "=r"(r[2]), "=r"(r[3]) : "r"(addr));
}
__device__ __forceinline__ void mma16816(float* d, const uint32_t* a, const uint32_t* b) {
    asm volatile("mma.sync.aligned.m16n8k16.row.col.f32.f16.f16.f32 "
        "{%0,%1,%2,%3}, {%4,%5,%6,%7}, {%8,%9}, {%0,%1,%2,%3};"
        : "+f"(d[0]), "+f"(d[1]), "+f"(d[2]), "+f"(d[3])
        : "r"(a[0]), "r"(a[1]), "r"(a[2]), "r"(a[3]), "r"(b[0]), "r"(b[1]));
}
#define CP16(dst, src) \
    asm volatile("cp.async.cg.shared.global [%0], [%1], 16;" :: "r"(dst), "l"(src) : "memory")
#define CP_COMMIT() asm volatile("cp.async.commit_group;" ::: "memory")
#define CP_WAIT1() asm volatile("cp.async.wait_group 1;" ::: "memory")

// SMEM stage: A tile + B tile, each 128 rows x 32 fp16, row stride 80B.
#define ROW_B 80
#define OFF_A 0
#define OFF_B 10240
#define STAGE_B 20480
#define SM_TOT (2 * STAGE_B)

// D[M,N] = epi(scale * A[M,K] @ B[N,K]^T), fp16 inputs, single-pass HMMA,
// 2-stage cp.async. CTA 128x128, BK=32, 256 thr = 8 warps (2M x 4N), warp 64x32.
__global__ void __launch_bounds__(256, 2) gemm_fp16(
    const __half* __restrict__ A, const __half* __restrict__ B,
    float* __restrict__ C, __half* __restrict__ O,
    int K, int lda, int ldb, int ldc,
    long sA, long sB, long sC,
    const float* __restrict__ bias, const float* __restrict__ residual,
    float scale, int act, int pe)
{
    extern __shared__ char sm[];
    uint32_t sb = smem_u32(sm);

    int tid = threadIdx.x, wid = tid >> 5, lane = tid & 31;
    long bz = blockIdx.z;
    A += bz * sA; B += bz * sB;
    if (C) C += bz * sC;
    if (O) O += bz * sC;
    const float* res = residual ? residual + bz * sC : nullptr;
    long row0 = (long)blockIdx.y * 128, col0 = (long)blockIdx.x * 128;

    int wm = wid >> 2, wn = wid & 3;     // 2 x 4 warp grid
    int m0w = wm * 64, n0w = wn * 32;

    float acc[4][4][4];
#pragma unroll
    for (int i = 0; i < 4; i++)
#pragma unroll
        for (int j = 0; j < 4; j++)
#pragma unroll
            for (int e = 0; e < 4; e++) acc[i][j][e] = 0.f;

    // loader: row = tid>>1 (0..127), 16B groups sg, sg+1 of 4 per row-chunk
    const int r_ld = tid >> 1;
    const int sg = (tid & 1) * 2;
    const int NC = K >> 5;

    const __half* a_src = A + (row0 + r_ld) * lda + sg * 8;
    const __half* b_src = B + (col0 + r_ld) * ldb + sg * 8;
    const uint32_t stA = sb + OFF_A + r_ld * ROW_B + sg * 16;
    const uint32_t stB = sb + OFF_B + r_ld * ROW_B + sg * 16;

    auto issue = [&](int c, uint32_t bofs) {
        long ko = (long)c * 32;
        CP16(stA + bofs,      a_src + ko);
        CP16(stA + bofs + 16, a_src + ko + 8);
        CP16(stB + bofs,      b_src + ko);
        CP16(stB + bofs + 16, b_src + ko + 8);
    };

    // ldmatrix addresses (stage 0 base; add bofs, + ks*32 per k16 step)
    uint32_t a_addr[4], b_addr[2];
#pragma unroll
    for (int i = 0; i < 4; i++) {
        uint32_t r = m0w + i * 16 + (lane & 15);
        a_addr[i] = sb + OFF_A + r * ROW_B + (lane >> 4) * 16;
    }
#pragma unroll
    for (int jp = 0; jp < 2; jp++) {     // pair of n-tiles (2jp, 2jp+1)
        uint32_t r = n0w + jp * 16 + ((lane >> 4) << 3) + (lane & 7);
        b_addr[jp] = sb + OFF_B + r * ROW_B + ((lane >> 3) & 1) * 16;
    }

    issue(0, 0); CP_COMMIT();
    if (NC > 1) issue(1, STAGE_B);
    CP_COMMIT();

    for (int c = 0; c < NC; c++) {
        CP_WAIT1();
        __syncthreads();
        uint32_t bofs = (c & 1) * STAGE_B;
#pragma unroll
        for (int ks = 0; ks < 2; ks++) {
            uint32_t ah[4][4], bh[2][4];
#pragma unroll
            for (int i = 0; i < 4; i++)
                ldsm4(ah[i], a_addr[i] + bofs + ks * 32);
#pragma unroll
            for (int jp = 0; jp < 2; jp++)
                ldsm4(bh[jp], b_addr[jp] + bofs + ks * 32);
#pragma unroll
            for (int i = 0; i < 4; i++)
#pragma unroll
                for (int j = 0; j < 4; j++)
                    mma16816(acc[i][j], ah[i], &bh[j >> 1][(j & 1) * 2]);
        }
        __syncthreads();
        if (c + 2 < NC) issue(c + 2, (c & 1) * STAGE_B);
        CP_COMMIT();
    }

    // epilogue: thread holds C[r1][cc..cc+1], C[r1+8][cc..cc+1] per (i,j)
#pragma unroll
    for (int i = 0; i < 4; i++) {
        long r1 = row0 + m0w + i * 16 + (lane >> 2);
        long r2 = r1 + 8;
#pragma unroll
        for (int j = 0; j < 4; j++) {
            long cc = col0 + n0w + j * 8 + 2 * (lane & 3);
            float2 bi = bias ? *(const float2*)(bias + cc) : make_float2(0.f, 0.f);
            float v0 = acc[i][j][0] * scale + bi.x;
            float v1 = acc[i][j][1] * scale + bi.y;
            float v2 = acc[i][j][2] * scale + bi.x;
            float v3 = acc[i][j][3] * scale + bi.y;
            if (act) { v0 = gelu_f(v0); v1 = gelu_f(v1); v2 = gelu_f(v2); v3 = gelu_f(v3); }
            if (res) {
                float2 q1 = *(const float2*)(res + r1 * ldc + cc);
                float2 q2 = *(const float2*)(res + r2 * ldc + cc);
                v0 += q1.x; v1 += q1.y; v2 += q2.x; v3 += q2.y;
            }
            if (pe) {
                float d0 = expf((float)cc * (-2.0f / 1024.0f) * 6.9077552789821370521f);
                float d1 = expf((float)(cc + 1) * (-2.0f / 1024.0f) * 6.9077552789821370521f);
                int s1 = (int)(r1 & (S_LEN - 1)), s2 = (int)(r2 & (S_LEN - 1));
                float a10 = s1 * d0, a11 = s1 * d1, a20 = s2 * d0, a21 = s2 * d1;
                v0 += (s1 & 1) ? cosf(a10) : sinf(a10);
                v1 += (s1 & 1) ? cosf(a11) : sinf(a11);
                v2 += (s2 & 1) ? cosf(a20) : sinf(a20);
                v3 += (s2 & 1) ? cosf(a21) : sinf(a21);
            }
            if (C) {
                *(float2*)(C + r1 * ldc + cc) = make_float2(v0, v1);
                *(float2*)(C + r2 * ldc + cc) = make_float2(v2, v3);
            }
            if (O) {
                *(uint32_t*)(O + r1 * ldc + cc) = h2_bits(__floats2half2_rn(v0, v1));
                *(uint32_t*)(O + r2 * ldc + cc) = h2_bits(__floats2half2_rn(v2, v3));
            }
        }
    }
}

// fused fp32 -> fp16 convert of 5 tensors, grid-stride over float4s
__global__ void cvt5_kernel(const float* s0, __half* d0, long n0,
                            const float* s1, __half* d1, long n1,
                            const float* s2, __half* d2, long n2,
                            const float* s3, __half* d3, long n3,
                            const float* s4, __half* d4, long n4)
{
    long tot = n0 + n1 + n2 + n3 + n4;
    long i = (long)blockIdx.x * blockDim.x + threadIdx.x;
    long stride = (long)gridDim.x * blockDim.x;
    for (; i < tot; i += stride) {
        const float* s; __half* d; long k = i;
        if (k < n0) { s = s0; d = d0; }
        else if ((k -= n0) < n1) { s = s1; d = d1; }
        else if ((k -= n1) < n2) { s = s2; d = d2; }
        else if ((k -= n2) < n3) { s = s3; d = d3; }
        else { k -= n3; s = s4; d = d4; }
        float4 f = ((const float4*)s)[k];
        uint2 h;
        h.x = h2_bits(__floats2half2_rn(f.x, f.y));
        h.y = h2_bits(__floats2half2_rn(f.z, f.w));
        ((uint2*)d)[k] = h;
    }
}

// dst[b][c][s] = qkv[b, s, co + c], vectorized 64x64 tile (uint4 both sides)
__global__ void transpose_h(const __half* __restrict__ q,
                            __half* __restrict__ dst_, int co)
{
    __shared__ __half t[64][65];
    int b = blockIdx.z;
    int s0 = blockIdx.x * 64, c0 = blockIdx.y * 64;
    int r = threadIdx.x >> 3;      // 0..31
    int g = threadIdx.x & 7;       // 0..7 (8-half group)
    const __half* src = q + (long)b * S_LEN * 3 * C_DIM + co;
#pragma unroll
    for (int rr = r; rr < 64; rr += 32) {
        uint4 v = *(const uint4*)(src + (long)(s0 + rr) * (3 * C_DIM) + c0 + g * 8);
        __half tmp[8];
        *(uint4*)tmp = v;
#pragma unroll
        for (int e = 0; e < 8; e++) t[rr][g * 8 + e] = tmp[e];
    }
    __syncthreads();
    __half* dst = dst_ + (long)b * C_DIM * S_LEN;
#pragma unroll
    for (int rr = r; rr < 64; rr += 32) {   // c index
        __half tmp[8];
#pragma unroll
        for (int e = 0; e < 8; e++) tmp[e] = t[g * 8 + e][rr];
        *(uint4*)(dst + (long)(c0 + rr) * S_LEN + s0 + g * 8) = *(uint4*)tmp;
    }
}

// layernorm over last dim (1024), fp32 in -> fp16 out
__global__ void layernorm_kernel(const float* __restrict__ h,
                                 const float* __restrict__ g,
                                 const float* __restrict__ b,
                                 __half* __restrict__ oh)
{
    __shared__ float sa[8], sb2[8];
    long row = blockIdx.x;
    const float* p = h + row * C_DIM;
    int tid = threadIdx.x;
    float v[4];
    float s1 = 0.f, s2 = 0.f;
#pragma unroll
    for (int i = 0; i < 4; i++) {
        v[i] = p[tid + i * 256];
        s1 += v[i];
        s2 += v[i] * v[i];
    }
#pragma unroll
    for (int o = 16; o > 0; o >>= 1) {
        s1 += __shfl_down_sync(0xffffffffu, s1, o);
        s2 += __shfl_down_sync(0xffffffffu, s2, o);
    }
    int lane = tid & 31, w = tid >> 5;
    if (lane == 0) { sa[w] = s1; sb2[w] = s2; }
    __syncthreads();
    if (tid < 32) {
        s1 = (tid < 8) ? sa[tid] : 0.f;
        s2 = (tid < 8) ? sb2[tid] : 0.f;
#pragma unroll
        for (int o = 4; o > 0; o >>= 1) {
            s1 += __shfl_down_sync(0xffffffffu, s1, o);
            s2 += __shfl_down_sync(0xffffffffu, s2, o);
        }
        if (tid == 0) { sa[0] = s1; sb2[0] = s2; }
    }
    __syncthreads();
    float mu = sa[0] * (1.0f / 1024.0f);
    float var = sb2[0] * (1.0f / 1024.0f) - mu * mu;
    float inv = rsqrtf(var + 1e-5f);
#pragma unroll
    for (int i = 0; i < 4; i++) {
        int c = tid + i * 256;
        float y = (v[i] - mu) * inv * g[c] + b[c];
        oh[row * C_DIM + c] = __float2half_rn(y);
    }
}

// softmax over last dim (1024), fp32 in -> fp16 out
__global__ void softmax_kernel(const float* __restrict__ att,
                               __half* __restrict__ oh)
{
    __shared__ float sh[8];
    long row = blockIdx.x;
    const float* p = att + row * C_DIM;
    int tid = threadIdx.x;
    float v[4];
    float m = -INFINITY;
#pragma unroll
    for (int i = 0; i < 4; i++) {
        v[i] = p[tid + i * 256];
        m = fmaxf(m, v[i]);
    }
#pragma unroll
    for (int o = 16; o > 0; o >>= 1)
        m = fmaxf(m, __shfl_down_sync(0xffffffffu, m, o));
    int lane = tid & 31, w = tid >> 5;
    if (lane == 0) sh[w] = m;
    __syncthreads();
    if (tid < 32) {
        m = (tid < 8) ? sh[tid] : -INFINITY;
#pragma unroll
        for (int o = 4; o > 0; o >>= 1)
            m = fmaxf(m, __shfl_down_sync(0xffffffffu, m, o));
        if (tid == 0) sh[0] = m;
    }
    __syncthreads();
    m = sh[0];
    __syncthreads();
    float e[4];
    float s = 0.f;
#pragma unroll
    for (int i = 0; i < 4; i++) {
        e[i] = expf(v[i] - m);
        s += e[i];
    }
#pragma unroll
    for (int o = 16; o > 0; o >>= 1)
        s += __shfl_down_sync(0xffffffffu, s, o);
    if (lane == 0) sh[w] = s;
    __syncthreads();
    if (tid < 32) {
        s = (tid < 8) ? sh[tid] : 0.f;
#pragma unroll
        for (int o = 4; o > 0; o >>= 1)
            s += __shfl_down_sync(0xffffffffu, s, o);
        if (tid == 0) sh[0] = s;
    }
    __syncthreads();
    float inv = 1.0f / sh[0];
#pragma unroll
    for (int i = 0; i < 4; i++) {
        int c = tid + i * 256;
        oh[row * C_DIM + c] = __float2half_rn(e[i] * inv);
    }
}

static void launch_gemm(const __half* A, const __half* B,
                        float* C, __half* O,
                        int M, int N, int K, int lda, int ldb, int ldc,
                        long sA, long sB, long sC, int batches,
                        const float* bias, const float* residual,
                        float scale, int act, int pe)
{
    dim3 grid(N / 128, M / 128, batches);
    gemm_fp16<<<grid, 256, SM_TOT>>>(A, B, C, O, K, lda, ldb, ldc,
                                     sA, sB, sC, bias, residual, scale, act, pe);
}

extern "C" void kernel_launch(void* const* d_in, const int* in_sizes, int n_in,
                              void* d_out, int out_size)
{
    const float* x        = (const float*)d_in[0];
    const float* fc_in_w  = (const float*)d_in[1];
    const float* fc_in_b  = (const float*)d_in[2];
    const float* ln_g     = (const float*)d_in[3];
    const float* ln_b     = (const float*)d_in[4];
    const float* qkv_w    = (const float*)d_in[5];
    const float* qkv_b    = (const float*)d_in[6];
    const float* proj_w   = (const float*)d_in[7];
    const float* proj_b   = (const float*)d_in[8];
    const float* fc_out_w = (const float*)d_in[9];
    const float* fc_out_b = (const float*)d_in[10];
    float* out = (float*)d_out;

    cudaFuncSetAttribute(gemm_fp16, cudaFuncAttributeMaxDynamicSharedMemorySize, SM_TOT);

    __half *wh, *xh, *ah, *qh, *kt, *vt, *m1, *smh;
    float *h0, *att, *pred;
    cudaGetSymbolAddress((void**)&wh, g_w_h);
    cudaGetSymbolAddress((void**)&xh, g_x_h);
    cudaGetSymbolAddress((void**)&ah, g_a_h);
    cudaGetSymbolAddress((void**)&qh, g_qkv_h);
    cudaGetSymbolAddress((void**)&kt, g_kt_h);
    cudaGetSymbolAddress((void**)&vt, g_vt_h);
    cudaGetSymbolAddress((void**)&m1, g_m1_h);
    cudaGetSymbolAddress((void**)&smh, g_sm_h);
    cudaGetSymbolAddress((void**)&h0, g_h0);
    cudaGetSymbolAddress((void**)&att, g_att);
    cudaGetSymbolAddress((void**)&pred, g_pred);

    // convert all inputs/weights to fp16 in ONE launch
    cvt5_kernel<<<1024, 256>>>(
        x, xh, (long)M_TOT * C_DIM / 4,
        fc_in_w, wh + W_FCIN, (long)C_DIM * C_DIM / 4,
        qkv_w, wh + W_QKV, (long)4 * 3 * C_DIM * C_DIM / 4,
        proj_w, wh + W_PROJ, (long)4 * C_DIM * C_DIM / 4,
        fc_out_w, wh + W_FCOUT, (long)C_DIM * C_DIM / 4);

    // h0 = x @ fc_in_w^T + fc_in_b    (fp32 out only)
    launch_gemm(xh, wh + W_FCIN, h0, nullptr,
                M_TOT, C_DIM, C_DIM, C_DIM, C_DIM, C_DIM, 0, 0, 0, 1,
                fc_in_b, nullptr, 1.0f, 0, 0);

    // a = fp16(layernorm(h0))
    layernorm_kernel<<<M_TOT, 256>>>(h0, ln_g, ln_b, ah);

    for (int i = 0; i < 4; i++) {
        long wq = W_QKV + (long)i * 3 * C_DIM * C_DIM;
        long wp = W_PROJ + (long)i * C_DIM * C_DIM;

        // qkv = fp16(gelu(a @ qkv_w[i]^T + qkv_b[i]))
        launch_gemm(ah, wh + wq, nullptr, qh,
                    M_TOT, 3 * C_DIM, C_DIM, C_DIM, C_DIM, 3 * C_DIM, 0, 0, 0, 1,
                    qkv_b + (long)i * 3 * C_DIM, nullptr, 1.0f, 1, 0);

        // kT, vT transposes (vectorized)
        transpose_h<<<dim3(S_LEN / 64, C_DIM / 64, NB), 256>>>(qh, kt, C_DIM);
        transpose_h<<<dim3(S_LEN / 64, C_DIM / 64, NB), 256>>>(qh, vt, 2 * C_DIM);

        // M1[c'][c] = sum_t v[t][c'] k[t][c]  = (k^T v)^T   (NT: A=vT, B=kT; batched)
        launch_gemm(vt, kt, nullptr, m1,
                    C_DIM, C_DIM, S_LEN, S_LEN, S_LEN, C_DIM,
                    (long)C_DIM * S_LEN, (long)C_DIM * S_LEN, (long)C_DIM * C_DIM,
                    NB, nullptr, nullptr, 1.0f, 0, 0);

        // att = q @ M1^T / 1024 = (q@k^T/C)@v   (fp32 out, batched; q strided in qkv)
        launch_gemm(qh, m1, att, nullptr,
                    S_LEN, C_DIM, C_DIM, 3 * C_DIM, C_DIM, C_DIM,
                    (long)S_LEN * 3 * C_DIM, (long)C_DIM * C_DIM, (long)S_LEN * C_DIM,
                    NB, nullptr, nullptr, 1.0f / 1024.0f, 0, 0);

        // sm = fp16(softmax(att))
        softmax_kernel<<<M_TOT, 256>>>(att, smh);

        // a = fp16(gelu(sm @ proj_w[i]^T + proj_b[i]) [+ pred]); fp32 pred copy on i==0
        launch_gemm(smh, wh + wp, (i == 0) ? pred : nullptr, ah,
                    M_TOT, C_DIM, C_DIM, C_DIM, C_DIM, C_DIM, 0, 0, 0, 1,
                    proj_b + (long)i * C_DIM, (i == 0) ? nullptr : pred, 1.0f, 1, 0);
    }

    // out = a @ fc_out_w^T + fc_out_b + pose_enc
    launch_gemm(ah, wh + W_FCOUT, out, nullptr,
                M_TOT, C_DIM, C_DIM, C_DIM, C_DIM, C_DIM, 0, 0, 0, 1,
                fc_out_b, nullptr, 1.0f, 0, 1);
}